// round 2
// baseline (speedup 1.0000x reference)
#include <cuda_runtime.h>
#include <math.h>

// Problem constants
#define B_SZ 1024
#define T_SZ 128
#define H_SZ 256
#define NG   1024            // 4*H
#define KC   512             // combined K = H (x) + H (h)
#define BH   (B_SZ * H_SZ)   // 262144 elements per [B,H] slab

// ---------------------------------------------------------------------------
// Device scratch (static; zero-initialized at module load; no cudaMalloc)
// ---------------------------------------------------------------------------
__device__ float g_xr [T_SZ * BH];    // relu(x), time-major [T][B][H]
__device__ float g_hs0[T_SZ * BH];    // layer-0 hidden outputs [T][B][H]
__device__ float g_h1 [2][BH];        // layer-1 hidden, double buffered
__device__ float g_c  [2][BH];        // cell state per layer (zeroed each launch)
__device__ float g_zero[BH];          // never written -> stays zero
__device__ float g_W  [2][KC * NG];   // combined, gate-interleaved weights [K][N']
__device__ float g_bias[2][NG];       // combined, gate-interleaved bias

// ---------------------------------------------------------------------------
// Helpers
// ---------------------------------------------------------------------------
__device__ __forceinline__ unsigned long long pack2(float lo, float hi) {
    return ((unsigned long long)__float_as_uint(hi) << 32) |
            (unsigned long long)__float_as_uint(lo);
}
__device__ __forceinline__ float lo2(unsigned long long v) {
    return __uint_as_float((unsigned)(v & 0xffffffffull));
}
__device__ __forceinline__ float hi2(unsigned long long v) {
    return __uint_as_float((unsigned)(v >> 32));
}
// packed fp32x2 FMA: d = a*b + d (lanewise). 2x throughput vs 3-reg FFMA on sm_10x.
__device__ __forceinline__ void ffma2(unsigned long long& d,
                                      unsigned long long a,
                                      unsigned long long b) {
    asm("fma.rn.f32x2 %0, %1, %2, %0;" : "+l"(d) : "l"(a), "l"(b));
}
__device__ __forceinline__ float sigm(float x) {
    return 1.0f / (1.0f + expf(-x));
}

// ---------------------------------------------------------------------------
// Prep: build gate-interleaved combined weights.
// W_perm[layer][k][n'] with n' = 4*j + g  ->  original gate column n = g*256 + j
//   k <  256 : w_ih[n][k]
//   k >= 256 : w_hh[n][k-256]
// ---------------------------------------------------------------------------
__global__ void prep_weights(const float* __restrict__ wih0,
                             const float* __restrict__ whh0,
                             const float* __restrict__ wih1,
                             const float* __restrict__ whh1) {
    int id = blockIdx.x * blockDim.x + threadIdx.x;   // [0, 2*512*1024)
    if (id >= 2 * KC * NG) return;
    int layer = id / (KC * NG);
    int rem   = id % (KC * NG);
    int k  = rem / NG;
    int np = rem % NG;
    int j  = np >> 2;
    int g  = np & 3;
    int n  = g * H_SZ + j;
    const float* wih = layer ? wih1 : wih0;
    const float* whh = layer ? whh1 : whh0;
    float v = (k < H_SZ) ? wih[n * H_SZ + k] : whh[n * H_SZ + (k - H_SZ)];
    g_W[layer][k * NG + np] = v;
}

// Prep: combined bias (gate-interleaved) + zero the cell states.
__global__ void prep_misc(const float* __restrict__ bih0,
                          const float* __restrict__ bhh0,
                          const float* __restrict__ bih1,
                          const float* __restrict__ bhh1) {
    int id = blockIdx.x * blockDim.x + threadIdx.x;
    // first 2*BH items: zero cells
    if (id < 2 * BH) {
        g_c[0][id < BH ? id : 0] = 0.0f;   // avoid branchy index math:
    }
    if (id < BH)            g_c[0][id] = 0.0f;
    else if (id < 2 * BH)   g_c[1][id - BH] = 0.0f;
    else if (id < 2 * BH + 2 * NG) {
        int r = id - 2 * BH;
        int layer = r / NG;
        int np = r % NG;
        int j = np >> 2, g = np & 3;
        int n = g * H_SZ + j;
        const float* bi = layer ? bih1 : bih0;
        const float* bh = layer ? bhh1 : bhh0;
        g_bias[layer][np] = bi[n] + bh[n];
    }
}

// ---------------------------------------------------------------------------
// relu + [B,T,H] -> [T,B,H] transpose (vectorized float4)
// ---------------------------------------------------------------------------
__global__ void relu_transpose(const float* __restrict__ x) {
    int id = blockIdx.x * blockDim.x + threadIdx.x;   // [0, T*B*64)
    if (id >= T_SZ * B_SZ * (H_SZ / 4)) return;
    int t   = id / (B_SZ * (H_SZ / 4));
    int rem = id % (B_SZ * (H_SZ / 4));
    int b   = rem / (H_SZ / 4);
    int e4  = rem % (H_SZ / 4);
    const float4 v = *(const float4*)(x + (size_t)b * T_SZ * H_SZ + t * H_SZ + e4 * 4);
    float4 r;
    r.x = fmaxf(v.x, 0.f); r.y = fmaxf(v.y, 0.f);
    r.z = fmaxf(v.z, 0.f); r.w = fmaxf(v.w, 0.f);
    *(float4*)(g_xr + (size_t)t * BH + b * H_SZ + e4 * 4) = r;
}

// ---------------------------------------------------------------------------
// One LSTM step: gates = [x_t | h_{t-1}] @ W_perm + bias  (M=1024,N=1024,K=512)
// BM=128, BN=64, BK=16, 256 threads, micro-tile 8x4 via f32x2 pairs.
// Each thread's 4 N-columns = {i,f,g,o} of one hidden unit -> fused pointwise.
// ---------------------------------------------------------------------------
__global__ __launch_bounds__(256) void lstm_step(int layer, int t) {
    const float* xsrc = (layer == 0) ? (g_xr + (size_t)t * BH)
                                     : (g_hs0 + (size_t)t * BH);
    const float* hin  = (t == 0) ? g_zero
                      : (layer == 0) ? (g_hs0 + (size_t)(t - 1) * BH)
                                     : g_h1[(t - 1) & 1];
    float* hout = (layer == 0) ? (g_hs0 + (size_t)t * BH) : g_h1[t & 1];
    float* c    = g_c[layer];
    const float* W    = g_W[layer];
    const float* bias = g_bias[layer];

    __shared__ __align__(16) float As[16][132];              // [BK][BM+pad]
    __shared__ __align__(16) unsigned long long Bsd[16][64]; // dup-packed B

    const int tid = threadIdx.x;
    const int tx  = tid & 15;         // N direction (16 x 4 cols)
    const int ty  = tid >> 4;         // M direction (16 x 8 rows)
    const int n0  = blockIdx.x * 64;
    const int m0  = blockIdx.y * 128;

    unsigned long long acc[4][4];     // [m-pair][n], lo=row 2mp, hi=row 2mp+1
    #pragma unroll
    for (int n = 0; n < 4; n++) {
        float bv = bias[n0 + tx * 4 + n];
        unsigned long long d = pack2(bv, bv);
        #pragma unroll
        for (int mp = 0; mp < 4; mp++) acc[mp][n] = d;
    }

    for (int kc = 0; kc < KC / 16; kc++) {
        const int kk = kc * 16;
        const float* src = (kk < H_SZ) ? (xsrc + kk) : (hin + (kk - H_SZ));

        // Load A tile (128 rows x 16 k), transpose into As[k][m]
        #pragma unroll
        for (int i = 0; i < 2; i++) {
            int idx = tid + i * 256;          // 0..511
            int row = idx >> 2;
            int c4  = idx & 3;
            float4 v = *(const float4*)(src + (size_t)(m0 + row) * H_SZ + c4 * 4);
            As[c4 * 4 + 0][row] = v.x;
            As[c4 * 4 + 1][row] = v.y;
            As[c4 * 4 + 2][row] = v.z;
            As[c4 * 4 + 3][row] = v.w;
        }
        // Load B tile (16 k x 64 n) and duplicate-pack for f32x2
        {
            int r  = tid >> 4;
            int c4 = tid & 15;
            float4 v = *(const float4*)(W + (size_t)(kk + r) * NG + n0 + c4 * 4);
            Bsd[r][c4 * 4 + 0] = pack2(v.x, v.x);
            Bsd[r][c4 * 4 + 1] = pack2(v.y, v.y);
            Bsd[r][c4 * 4 + 2] = pack2(v.z, v.z);
            Bsd[r][c4 * 4 + 3] = pack2(v.w, v.w);
        }
        __syncthreads();

        #pragma unroll
        for (int k = 0; k < 16; k++) {
            ulonglong2 a01 = *(const ulonglong2*)&As[k][ty * 8];
            ulonglong2 a23 = *(const ulonglong2*)&As[k][ty * 8 + 4];
            unsigned long long ap0 = a01.x, ap1 = a01.y, ap2 = a23.x, ap3 = a23.y;
            #pragma unroll
            for (int n = 0; n < 4; n++) {
                unsigned long long bd = Bsd[k][tx * 4 + n];
                ffma2(acc[0][n], ap0, bd);
                ffma2(acc[1][n], ap1, bd);
                ffma2(acc[2][n], ap2, bd);
                ffma2(acc[3][n], ap3, bd);
            }
        }
        __syncthreads();
    }

    // Fused pointwise LSTM update; this thread owns hidden unit j for 8 rows.
    const int j = (n0 >> 2) + tx;
    #pragma unroll
    for (int mp = 0; mp < 4; mp++) {
        #pragma unroll
        for (int half = 0; half < 2; half++) {
            int gm = m0 + ty * 8 + mp * 2 + half;
            float gi = half ? hi2(acc[mp][0]) : lo2(acc[mp][0]);
            float gf = half ? hi2(acc[mp][1]) : lo2(acc[mp][1]);
            float gg = half ? hi2(acc[mp][2]) : lo2(acc[mp][2]);
            float go = half ? hi2(acc[mp][3]) : lo2(acc[mp][3]);
            int idx = gm * H_SZ + j;
            float cold = c[idx];
            float cn = sigm(gf) * cold + sigm(gi) * tanhf(gg);
            float hn = sigm(go) * tanhf(cn);
            c[idx]    = cn;
            hout[idx] = hn;
        }
    }
}

// ---------------------------------------------------------------------------
// FC head: out[b] = sigmoid( relu(h @ fc1_w.T + fc1_b) @ fc2_w.T + fc2_b )
// One block (128 threads) per batch row.
// ---------------------------------------------------------------------------
__global__ __launch_bounds__(128) void fc_head(const float* __restrict__ fc1w,
                                               const float* __restrict__ fc1b,
                                               const float* __restrict__ fc2w,
                                               const float* __restrict__ fc2b,
                                               float* __restrict__ out) {
    __shared__ float sh[H_SZ];
    __shared__ float red[128];
    const int b = blockIdx.x;
    const int t = threadIdx.x;
    const float* h = g_h1[(T_SZ - 1) & 1];   // final layer-1 hidden (t=127 -> buf 1)
    sh[t]       = h[b * H_SZ + t];
    sh[t + 128] = h[b * H_SZ + t + 128];
    __syncthreads();
    float acc = 0.f;
    const float* wr = fc1w + t * H_SZ;
    #pragma unroll 8
    for (int k = 0; k < H_SZ; k++) acc += sh[k] * wr[k];
    acc += fc1b[t];
    acc = fmaxf(acc, 0.f) * fc2w[t];
    red[t] = acc;
    __syncthreads();
    for (int s = 64; s > 0; s >>= 1) {
        if (t < s) red[t] += red[t + s];
        __syncthreads();
    }
    if (t == 0) out[b] = 1.f / (1.f + expf(-(red[0] + fc2b[0])));
}

// ---------------------------------------------------------------------------
// Launch
// ---------------------------------------------------------------------------
extern "C" void kernel_launch(void* const* d_in, const int* in_sizes, int n_in,
                              void* d_out, int out_size) {
    const float* x    = (const float*)d_in[0];
    const float* wih0 = (const float*)d_in[1];
    const float* whh0 = (const float*)d_in[2];
    const float* bih0 = (const float*)d_in[3];
    const float* bhh0 = (const float*)d_in[4];
    const float* wih1 = (const float*)d_in[5];
    const float* whh1 = (const float*)d_in[6];
    const float* bih1 = (const float*)d_in[7];
    const float* bhh1 = (const float*)d_in[8];
    const float* fc1w = (const float*)d_in[9];
    const float* fc1b = (const float*)d_in[10];
    const float* fc2w = (const float*)d_in[11];
    const float* fc2b = (const float*)d_in[12];
    float* out = (float*)d_out;

    // Weight prep + cell zeroing (every launch: deterministic)
    prep_weights<<<(2 * KC * NG + 255) / 256, 256>>>(wih0, whh0, wih1, whh1);
    prep_misc<<<(2 * BH + 2 * NG + 255) / 256, 256>>>(bih0, bhh0, bih1, bhh1);

    // relu + time-major transpose
    relu_transpose<<<(T_SZ * B_SZ * (H_SZ / 4) + 255) / 256, 256>>>(x);

    dim3 grid(NG / 64, B_SZ / 128);   // 16 x 8 = 128 CTAs
    for (int t = 0; t < T_SZ; t++) lstm_step<<<grid, 256>>>(0, t);
    for (int t = 0; t < T_SZ; t++) lstm_step<<<grid, 256>>>(1, t);

    fc_head<<<B_SZ, 128>>>(fc1w, fc1b, fc2w, fc2b, out);
}

// round 5
// speedup vs baseline: 4.0478x; 4.0478x over previous
#include <cuda_runtime.h>
#include <cuda_bf16.h>
#include <cstdint>
#include <math.h>

#define B_SZ 1024
#define T_SZ 128
#define H_SZ 256
#define NG   1024            // 4*H
#define KC   512             // combined K (x | h)
#define BH   (B_SZ * H_SZ)

// ---------------------------------------------------------------------------
// Static device scratch (no cudaMalloc anywhere)
// ---------------------------------------------------------------------------
__device__ __align__(16) __nv_bfloat16 g_xr_hi [T_SZ * BH];
__device__ __align__(16) __nv_bfloat16 g_xr_lo [T_SZ * BH];
__device__ __align__(16) __nv_bfloat16 g_hs0_hi[T_SZ * BH];
__device__ __align__(16) __nv_bfloat16 g_hs0_lo[T_SZ * BH];
__device__ __align__(16) __nv_bfloat16 g_h1_hi [2][BH];
__device__ __align__(16) __nv_bfloat16 g_h1_lo [2][BH];
__device__ __align__(16) __nv_bfloat16 g_zero_bf[BH];      // never written -> zero
__device__ __align__(16) float         g_c[2][BH];
__device__ __align__(16) __nv_bfloat16 g_Wp_hi[2][NG * KC]; // [n'][K], n'=4j+g
__device__ __align__(16) __nv_bfloat16 g_Wp_lo[2][NG * KC];
__device__ __align__(16) float         g_biasP[2][NG];

// ---------------------------------------------------------------------------
// PTX helpers (sm_100 plain: cp.async + ldmatrix + mma.sync only)
// ---------------------------------------------------------------------------
__device__ __forceinline__ uint32_t smem_u32(const void* p) {
    uint32_t a;
    asm("{ .reg .u64 t; cvta.to.shared.u64 t, %1; cvt.u32.u64 %0, t; }" : "=r"(a) : "l"(p));
    return a;
}
__device__ __forceinline__ void cpasync16(uint32_t s, const void* g) {
    asm volatile("cp.async.cg.shared.global [%0], [%1], 16;" :: "r"(s), "l"(g));
}
#define CP_COMMIT() asm volatile("cp.async.commit_group;" ::: "memory")
#define CP_WAIT1()  asm volatile("cp.async.wait_group 1;" ::: "memory")
#define CP_WAIT0()  asm volatile("cp.async.wait_group 0;" ::: "memory")

#define LDSM4(r0, r1, r2, r3, addr) asm volatile( \
    "ldmatrix.sync.aligned.m8n8.x4.shared.b16 {%0,%1,%2,%3}, [%4];" \
    : "=r"(r0), "=r"(r1), "=r"(r2), "=r"(r3) : "r"(addr))

#define MMA16816(d, a, b) asm volatile( \
    "mma.sync.aligned.m16n8k16.row.col.f32.bf16.bf16.f32 " \
    "{%0,%1,%2,%3}, {%4,%5,%6,%7}, {%8,%9}, {%0,%1,%2,%3};" \
    : "+f"((d)[0]), "+f"((d)[1]), "+f"((d)[2]), "+f"((d)[3]) \
    : "r"((a)[0]), "r"((a)[1]), "r"((a)[2]), "r"((a)[3]), "r"((b)[0]), "r"((b)[1]))

// SMEM: 2 buffers x {Ahi,Alo,Bhi,Blo} tiles of 128 rows x 32 bf16, row pitch 80B
// (pad to 80B -> conflict-free ldmatrix). Gate staging reuses buffer space.
#define TILE_B   10240                 // 128*80
#define BUF_SZ   (4 * TILE_B)          // 40960
#define OFF_AHI(b) ((b) * BUF_SZ)
#define OFF_ALO(b) ((b) * BUF_SZ + TILE_B)
#define OFF_BHI(b) ((b) * BUF_SZ + 2 * TILE_B)
#define OFF_BLO(b) ((b) * BUF_SZ + 3 * TILE_B)
#define SMEM_TOTAL (2 * BUF_SZ)        // 81920; gates (128*132*4=67584) aliases

__device__ __forceinline__ float fsigm(float x) {
    x = fminf(fmaxf(x, -30.f), 30.f);
    return __fdividef(1.f, 1.f + __expf(-x));
}
__device__ __forceinline__ float ftanh(float x) {
    x = fminf(fmaxf(x, -15.f), 15.f);
    float e = __expf(2.f * x);
    return (e - 1.f) * __fdividef(1.f, e + 1.f);
}

// ---------------------------------------------------------------------------
// Prep kernels
// ---------------------------------------------------------------------------
__global__ void prep_weights(const float* __restrict__ wih0, const float* __restrict__ whh0,
                             const float* __restrict__ wih1, const float* __restrict__ whh1) {
    int id = blockIdx.x * blockDim.x + threadIdx.x;
    if (id >= 2 * NG * KC) return;
    int layer = id >> 19;
    int rem   = id & ((1 << 19) - 1);
    int np = rem >> 9;       // n' row
    int k  = rem & 511;
    int j = np >> 2, g = np & 3;
    int n = g * H_SZ + j;
    const float* wih = layer ? wih1 : wih0;
    const float* whh = layer ? whh1 : whh0;
    float w = (k < H_SZ) ? wih[n * H_SZ + k] : whh[n * H_SZ + (k - H_SZ)];
    __nv_bfloat16 hi = __float2bfloat16(w);
    __nv_bfloat16 lo = __float2bfloat16(w - __bfloat162float(hi));
    g_Wp_hi[layer][np * KC + k] = hi;
    g_Wp_lo[layer][np * KC + k] = lo;
}

__global__ void prep_misc(const float* __restrict__ bih0, const float* __restrict__ bhh0,
                          const float* __restrict__ bih1, const float* __restrict__ bhh1) {
    int id = blockIdx.x * blockDim.x + threadIdx.x;
    if (id < BH)          g_c[0][id] = 0.0f;
    else if (id < 2 * BH) g_c[1][id - BH] = 0.0f;
    else if (id < 2 * BH + 2 * NG) {
        int r = id - 2 * BH;
        int layer = r >> 10;
        int np = r & 1023;
        int j = np >> 2, g = np & 3;
        int n = g * H_SZ + j;
        const float* bi = layer ? bih1 : bih0;
        const float* bh = layer ? bhh1 : bhh0;
        g_biasP[layer][np] = bi[n] + bh[n];
    }
}

// relu + [B,T,H]->[T,B,H] + bf16 hi/lo split
__global__ void relu_split(const float* __restrict__ x) {
    int id = blockIdx.x * blockDim.x + threadIdx.x;
    if (id >= T_SZ * B_SZ * (H_SZ / 4)) return;
    int t   = id / (B_SZ * (H_SZ / 4));
    int rem = id % (B_SZ * (H_SZ / 4));
    int b   = rem / (H_SZ / 4);
    int e4  = rem % (H_SZ / 4);
    float4 v = *(const float4*)(x + (size_t)b * T_SZ * H_SZ + t * H_SZ + e4 * 4);
    v.x = fmaxf(v.x, 0.f); v.y = fmaxf(v.y, 0.f);
    v.z = fmaxf(v.z, 0.f); v.w = fmaxf(v.w, 0.f);
    size_t o = (size_t)t * BH + b * H_SZ + e4 * 4;
    __nv_bfloat16 hx = __float2bfloat16(v.x), hy = __float2bfloat16(v.y);
    __nv_bfloat16 hz = __float2bfloat16(v.z), hw = __float2bfloat16(v.w);
    *(__nv_bfloat162*)(g_xr_hi + o)     = __nv_bfloat162{hx, hy};
    *(__nv_bfloat162*)(g_xr_hi + o + 2) = __nv_bfloat162{hz, hw};
    *(__nv_bfloat162*)(g_xr_lo + o)     = __nv_bfloat162{
        __float2bfloat16(v.x - __bfloat162float(hx)), __float2bfloat16(v.y - __bfloat162float(hy))};
    *(__nv_bfloat162*)(g_xr_lo + o + 2) = __nv_bfloat162{
        __float2bfloat16(v.z - __bfloat162float(hz)), __float2bfloat16(v.w - __bfloat162float(hw))};
}

// ---------------------------------------------------------------------------
// LSTM wavefront u: layer 0 does t=u, layer 1 does t=u-1.
// grid (8, 8, 2), 256 threads. CTA tile 128(m) x 128(n'), K=512, BK=32.
// gates = [x|h] @ Wp  via bf16 hi/lo 3-product mma.sync; fused LSTM epilogue.
// ---------------------------------------------------------------------------
__global__ __launch_bounds__(256) void lstm_step_mma(int u) {
    const int layer = blockIdx.z;
    const int t = u - layer;
    if (t < 0 || t >= T_SZ) return;

    extern __shared__ char smem[];
    const uint32_t sb = smem_u32(smem);
    const int tid  = threadIdx.x;
    const int lane = tid & 31;
    const int wid  = tid >> 5;
    const int wm   = wid & 1;        // 2 m-warps (64 rows each)
    const int wn   = wid >> 1;       // 4 n-warps (32 cols each)
    const int n0 = blockIdx.x * 128;
    const int m0 = blockIdx.y * 128;

    // operand sources
    const __nv_bfloat16 *xh, *xl, *hh, *hl;
    if (layer == 0) {
        xh = g_xr_hi + (size_t)t * BH;  xl = g_xr_lo + (size_t)t * BH;
        if (t == 0) { hh = g_zero_bf; hl = g_zero_bf; }
        else { hh = g_hs0_hi + (size_t)(t - 1) * BH; hl = g_hs0_lo + (size_t)(t - 1) * BH; }
    } else {
        xh = g_hs0_hi + (size_t)t * BH; xl = g_hs0_lo + (size_t)t * BH;
        if (t == 0) { hh = g_zero_bf; hl = g_zero_bf; }
        else { hh = g_h1_hi[(t - 1) & 1]; hl = g_h1_lo[(t - 1) & 1]; }
    }
    __nv_bfloat16* out_hi = (layer == 0) ? (g_hs0_hi + (size_t)t * BH) : g_h1_hi[t & 1];
    __nv_bfloat16* out_lo = (layer == 0) ? (g_hs0_lo + (size_t)t * BH) : g_h1_lo[t & 1];
    float* cst = g_c[layer];
    const __nv_bfloat16* WH = g_Wp_hi[layer];
    const __nv_bfloat16* WL = g_Wp_lo[layer];

    // ---- chunk loader: 4 tiles (Ahi,Alo,Bhi,Blo) of 128x32 bf16 ----
    auto load_chunk = [&](int ck) {
        const int buf = ck & 1;
        const int kk = ck * 32;
        const __nv_bfloat16* ah = (kk < H_SZ) ? xh : hh;
        const __nv_bfloat16* al = (kk < H_SZ) ? xl : hl;
        const int koff = kk & (H_SZ - 1);
        #pragma unroll
        for (int i = 0; i < 2; i++) {
            int idx = tid + i * 256;          // 0..511
            int row = idx >> 2, c16 = idx & 3;
            size_t ge = (size_t)(m0 + row) * H_SZ + koff + c16 * 8;
            uint32_t so = sb + OFF_AHI(buf) + row * 80 + c16 * 16;
            cpasync16(so, ah + ge);
            cpasync16(so + TILE_B, al + ge);
        }
        #pragma unroll
        for (int i = 0; i < 2; i++) {
            int idx = tid + i * 256;
            int row = idx >> 2, c16 = idx & 3;
            size_t ge = (size_t)(n0 + row) * KC + kk + c16 * 8;
            uint32_t so = sb + OFF_BHI(buf) + row * 80 + c16 * 16;
            cpasync16(so, WH + ge);
            cpasync16(so + TILE_B, WL + ge);
        }
        CP_COMMIT();
    };

    float acc[4][4][4];
    #pragma unroll
    for (int a = 0; a < 4; a++)
        #pragma unroll
        for (int b = 0; b < 4; b++)
            #pragma unroll
            for (int q = 0; q < 4; q++) acc[a][b][q] = 0.f;

    load_chunk(0);

    // precomputed ldmatrix lane addressing
    const uint32_t a_lane = (uint32_t)((lane & 15) * 80 + ((lane >> 4) << 4));
    const uint32_t b_lane = (uint32_t)(((lane & 7) + ((lane >> 4) & 1) * 8) * 80 +
                                       ((lane >> 3) & 1) * 16);

    #pragma unroll 1
    for (int ck = 0; ck < 16; ck++) {
        const int buf = ck & 1;
        if (ck < 15) load_chunk(ck + 1);
        if (ck < 15) { CP_WAIT1(); } else { CP_WAIT0(); }
        __syncthreads();

        #pragma unroll
        for (int ks = 0; ks < 2; ks++) {
            const uint32_t kso = (uint32_t)(ks * 32);
            // B fragments: hi & lo, 4 n8-frags each
            uint32_t bhf[4][2], blf[4][2];
            #pragma unroll
            for (int blk = 0; blk < 2; blk++) {
                uint32_t ad = sb + OFF_BHI(buf) + (wn * 32 + blk * 16) * 80 + kso + b_lane;
                LDSM4(bhf[blk * 2][0], bhf[blk * 2][1], bhf[blk * 2 + 1][0], bhf[blk * 2 + 1][1], ad);
                LDSM4(blf[blk * 2][0], blf[blk * 2][1], blf[blk * 2 + 1][0], blf[blk * 2 + 1][1],
                      ad + TILE_B);
            }
            // A hi fragments -> 2 products
            uint32_t af[4][4];
            #pragma unroll
            for (int mf = 0; mf < 4; mf++) {
                uint32_t ad = sb + OFF_AHI(buf) + (wm * 64 + mf * 16) * 80 + kso + a_lane;
                LDSM4(af[mf][0], af[mf][1], af[mf][2], af[mf][3], ad);
            }
            #pragma unroll
            for (int mf = 0; mf < 4; mf++)
                #pragma unroll
                for (int nf = 0; nf < 4; nf++) {
                    MMA16816(acc[mf][nf], af[mf], bhf[nf]);
                    MMA16816(acc[mf][nf], af[mf], blf[nf]);
                }
            // A lo fragments -> 1 product
            #pragma unroll
            for (int mf = 0; mf < 4; mf++) {
                uint32_t ad = sb + OFF_ALO(buf) + (wm * 64 + mf * 16) * 80 + kso + a_lane;
                LDSM4(af[mf][0], af[mf][1], af[mf][2], af[mf][3], ad);
            }
            #pragma unroll
            for (int mf = 0; mf < 4; mf++)
                #pragma unroll
                for (int nf = 0; nf < 4; nf++)
                    MMA16816(acc[mf][nf], af[mf], bhf[nf]);
        }
        __syncthreads();
    }

    // ---- stage gates to SMEM (reuses tile buffers) ----
    float* gates = (float*)smem;      // [128][132]
    #pragma unroll
    for (int mf = 0; mf < 4; mf++)
        #pragma unroll
        for (int nf = 0; nf < 4; nf++) {
            int r = wm * 64 + mf * 16 + (lane >> 2);
            int cc = wn * 32 + nf * 8 + (lane & 3) * 2;
            gates[r * 132 + cc]           = acc[mf][nf][0];
            gates[r * 132 + cc + 1]       = acc[mf][nf][1];
            gates[(r + 8) * 132 + cc]     = acc[mf][nf][2];
            gates[(r + 8) * 132 + cc + 1] = acc[mf][nf][3];
        }
    __syncthreads();

    // ---- fused LSTM pointwise: 128 rows x 32 hidden units per CTA ----
    const int j0 = n0 >> 2;
    const float* bp = g_biasP[layer] + n0;
    #pragma unroll 4
    for (int i = 0; i < 16; i++) {
        int e = i * 256 + tid;
        int row = e >> 5, j = e & 31;
        float4 bq = *(const float4*)(bp + 4 * j);
        float4 gq = *(const float4*)(gates + row * 132 + 4 * j);
        float gi = gq.x + bq.x, gf = gq.y + bq.y, gg = gq.z + bq.z, go = gq.w + bq.w;
        size_t ci = (size_t)(m0 + row) * H_SZ + j0 + j;
        float cold = cst[ci];
        float cn = fsigm(gf) * cold + fsigm(gi) * ftanh(gg);
        float hn = fsigm(go) * ftanh(cn);
        cst[ci] = cn;
        __nv_bfloat16 hb = __float2bfloat16(hn);
        out_hi[ci] = hb;
        out_lo[ci] = __float2bfloat16(hn - __bfloat162float(hb));
    }
}

// ---------------------------------------------------------------------------
// FC head
// ---------------------------------------------------------------------------
__global__ __launch_bounds__(128) void fc_head(const float* __restrict__ fc1w,
                                               const float* __restrict__ fc1b,
                                               const float* __restrict__ fc2w,
                                               const float* __restrict__ fc2b,
                                               float* __restrict__ out) {
    __shared__ float sh[H_SZ];
    __shared__ float red[128];
    const int b = blockIdx.x, t = threadIdx.x;
    const __nv_bfloat16* hh = g_h1_hi[(T_SZ - 1) & 1];
    const __nv_bfloat16* hl = g_h1_lo[(T_SZ - 1) & 1];
    sh[t]       = __bfloat162float(hh[b * H_SZ + t])       + __bfloat162float(hl[b * H_SZ + t]);
    sh[t + 128] = __bfloat162float(hh[b * H_SZ + t + 128]) + __bfloat162float(hl[b * H_SZ + t + 128]);
    __syncthreads();
    float acc = 0.f;
    const float* wr = fc1w + t * H_SZ;
    #pragma unroll 8
    for (int k = 0; k < H_SZ; k++) acc += sh[k] * wr[k];
    acc += fc1b[t];
    acc = fmaxf(acc, 0.f) * fc2w[t];
    red[t] = acc;
    __syncthreads();
    for (int s = 64; s > 0; s >>= 1) {
        if (t < s) red[t] += red[t + s];
        __syncthreads();
    }
    if (t == 0) out[b] = 1.f / (1.f + expf(-(red[0] + fc2b[0])));
}

// ---------------------------------------------------------------------------
// Launch
// ---------------------------------------------------------------------------
extern "C" void kernel_launch(void* const* d_in, const int* in_sizes, int n_in,
                              void* d_out, int out_size) {
    const float* x    = (const float*)d_in[0];
    const float* wih0 = (const float*)d_in[1];
    const float* whh0 = (const float*)d_in[2];
    const float* bih0 = (const float*)d_in[3];
    const float* bhh0 = (const float*)d_in[4];
    const float* wih1 = (const float*)d_in[5];
    const float* whh1 = (const float*)d_in[6];
    const float* bih1 = (const float*)d_in[7];
    const float* bhh1 = (const float*)d_in[8];
    const float* fc1w = (const float*)d_in[9];
    const float* fc1b = (const float*)d_in[10];
    const float* fc2w = (const float*)d_in[11];
    const float* fc2b = (const float*)d_in[12];
    float* out = (float*)d_out;

    cudaFuncSetAttribute(lstm_step_mma, cudaFuncAttributeMaxDynamicSharedMemorySize, SMEM_TOTAL);

    prep_weights<<<(2 * NG * KC + 255) / 256, 256>>>(wih0, whh0, wih1, whh1);
    prep_misc<<<(2 * BH + 2 * NG + 255) / 256, 256>>>(bih0, bhh0, bih1, bhh1);
    relu_split<<<(T_SZ * B_SZ * (H_SZ / 4) + 255) / 256, 256>>>(x);

    dim3 grid(NG / 128, B_SZ / 128, 2);   // (8, 8, 2)
    for (int u = 0; u <= T_SZ; u++) lstm_step_mma<<<grid, 256, SMEM_TOTAL>>>(u);

    fc_head<<<B_SZ, 128>>>(fc1w, fc1b, fc2w, fc2b, out);
}

// round 6
// speedup vs baseline: 4.0538x; 1.0015x over previous
#include <cuda_runtime.h>
#include <cuda_bf16.h>
#include <cstdint>
#include <math.h>

#define B_SZ 1024
#define T_SZ 128
#define H_SZ 256
#define NG   1024            // 4*H
#define KC   512             // combined K (x | h)
#define BH   (B_SZ * H_SZ)

// ---------------------------------------------------------------------------
// Static device scratch (no cudaMalloc anywhere)
// ---------------------------------------------------------------------------
__device__ __align__(16) __nv_bfloat16 g_xr_hi [T_SZ * BH];
__device__ __align__(16) __nv_bfloat16 g_xr_lo [T_SZ * BH];
__device__ __align__(16) __nv_bfloat16 g_hs0_hi[T_SZ * BH];
__device__ __align__(16) __nv_bfloat16 g_hs0_lo[T_SZ * BH];
__device__ __align__(16) __nv_bfloat16 g_h1_hi [2][BH];
__device__ __align__(16) __nv_bfloat16 g_h1_lo [2][BH];
__device__ __align__(16) __nv_bfloat16 g_zero_bf[BH];      // never written -> zero
__device__ __align__(16) float         g_c[2][BH];
__device__ __align__(16) __nv_bfloat16 g_Wp_hi[2][NG * KC]; // [n'][K], n'=4j+g
__device__ __align__(16) __nv_bfloat16 g_Wp_lo[2][NG * KC];
__device__ __align__(16) float         g_biasP[2][NG];

// ---------------------------------------------------------------------------
// PTX helpers (plain sm_100: cp.async + ldmatrix + mma.sync)
// ---------------------------------------------------------------------------
__device__ __forceinline__ uint32_t smem_u32(const void* p) {
    uint32_t a;
    asm("{ .reg .u64 t; cvta.to.shared.u64 t, %1; cvt.u32.u64 %0, t; }" : "=r"(a) : "l"(p));
    return a;
}
__device__ __forceinline__ void cpasync16(uint32_t s, const void* g) {
    asm volatile("cp.async.cg.shared.global [%0], [%1], 16;" :: "r"(s), "l"(g));
}
#define CP_COMMIT() asm volatile("cp.async.commit_group;" ::: "memory")
#define CP_WAIT1()  asm volatile("cp.async.wait_group 1;" ::: "memory")
#define CP_WAIT0()  asm volatile("cp.async.wait_group 0;" ::: "memory")

#define LDSM4(r0, r1, r2, r3, addr) asm volatile( \
    "ldmatrix.sync.aligned.m8n8.x4.shared.b16 {%0,%1,%2,%3}, [%4];" \
    : "=r"(r0), "=r"(r1), "=r"(r2), "=r"(r3) : "r"(addr))

#define MMA16816(d, a, b) asm volatile( \
    "mma.sync.aligned.m16n8k16.row.col.f32.bf16.bf16.f32 " \
    "{%0,%1,%2,%3}, {%4,%5,%6,%7}, {%8,%9}, {%0,%1,%2,%3};" \
    : "+f"((d)[0]), "+f"((d)[1]), "+f"((d)[2]), "+f"((d)[3]) \
    : "r"((a)[0]), "r"((a)[1]), "r"((a)[2]), "r"((a)[3]), "r"((b)[0]), "r"((b)[1]))

// SMEM: 3 pipeline buffers. Per chunk (BK=32):
//   Ahi/Alo: 128 rows x 32 bf16, pitch 80B -> 10240B each
//   Bhi/Blo:  64 rows x 32 bf16, pitch 80B ->  5120B each
#define A_TILE_B 10240
#define B_TILE_B 5120
#define BUF_SZ   (2 * A_TILE_B + 2 * B_TILE_B)   // 30720
#define OFF_AHI(b) ((b) * BUF_SZ)
#define OFF_ALO(b) ((b) * BUF_SZ + A_TILE_B)
#define OFF_BHI(b) ((b) * BUF_SZ + 2 * A_TILE_B)
#define OFF_BLO(b) ((b) * BUF_SZ + 2 * A_TILE_B + B_TILE_B)
#define SMEM_TOTAL (3 * BUF_SZ)                  // 92160; gates [128][68] aliases

__device__ __forceinline__ float fsigm(float x) {
    x = fminf(fmaxf(x, -30.f), 30.f);
    return __fdividef(1.f, 1.f + __expf(-x));
}
__device__ __forceinline__ float ftanh(float x) {
    x = fminf(fmaxf(x, -15.f), 15.f);
    float e = __expf(2.f * x);
    return (e - 1.f) * __fdividef(1.f, e + 1.f);
}

// ---------------------------------------------------------------------------
// Prep kernels
// ---------------------------------------------------------------------------
__global__ void prep_weights(const float* __restrict__ wih0, const float* __restrict__ whh0,
                             const float* __restrict__ wih1, const float* __restrict__ whh1) {
    int id = blockIdx.x * blockDim.x + threadIdx.x;
    if (id >= 2 * NG * KC) return;
    int layer = id >> 19;
    int rem   = id & ((1 << 19) - 1);
    int np = rem >> 9;
    int k  = rem & 511;
    int j = np >> 2, g = np & 3;
    int n = g * H_SZ + j;
    const float* wih = layer ? wih1 : wih0;
    const float* whh = layer ? whh1 : whh0;
    float w = (k < H_SZ) ? wih[n * H_SZ + k] : whh[n * H_SZ + (k - H_SZ)];
    __nv_bfloat16 hi = __float2bfloat16(w);
    __nv_bfloat16 lo = __float2bfloat16(w - __bfloat162float(hi));
    g_Wp_hi[layer][np * KC + k] = hi;
    g_Wp_lo[layer][np * KC + k] = lo;
}

__global__ void prep_misc(const float* __restrict__ bih0, const float* __restrict__ bhh0,
                          const float* __restrict__ bih1, const float* __restrict__ bhh1) {
    int id = blockIdx.x * blockDim.x + threadIdx.x;
    if (id < BH)          g_c[0][id] = 0.0f;
    else if (id < 2 * BH) g_c[1][id - BH] = 0.0f;
    else if (id < 2 * BH + 2 * NG) {
        int r = id - 2 * BH;
        int layer = r >> 10;
        int np = r & 1023;
        int j = np >> 2, g = np & 3;
        int n = g * H_SZ + j;
        const float* bi = layer ? bih1 : bih0;
        const float* bh = layer ? bhh1 : bhh0;
        g_biasP[layer][np] = bi[n] + bh[n];
    }
}

// relu + [B,T,H]->[T,B,H] + bf16 hi/lo split
__global__ void relu_split(const float* __restrict__ x) {
    int id = blockIdx.x * blockDim.x + threadIdx.x;
    if (id >= T_SZ * B_SZ * (H_SZ / 4)) return;
    int t   = id / (B_SZ * (H_SZ / 4));
    int rem = id % (B_SZ * (H_SZ / 4));
    int b   = rem / (H_SZ / 4);
    int e4  = rem % (H_SZ / 4);
    float4 v = *(const float4*)(x + (size_t)b * T_SZ * H_SZ + t * H_SZ + e4 * 4);
    v.x = fmaxf(v.x, 0.f); v.y = fmaxf(v.y, 0.f);
    v.z = fmaxf(v.z, 0.f); v.w = fmaxf(v.w, 0.f);
    size_t o = (size_t)t * BH + b * H_SZ + e4 * 4;
    __nv_bfloat16 hx = __float2bfloat16(v.x), hy = __float2bfloat16(v.y);
    __nv_bfloat16 hz = __float2bfloat16(v.z), hw = __float2bfloat16(v.w);
    *(__nv_bfloat162*)(g_xr_hi + o)     = __nv_bfloat162{hx, hy};
    *(__nv_bfloat162*)(g_xr_hi + o + 2) = __nv_bfloat162{hz, hw};
    *(__nv_bfloat162*)(g_xr_lo + o)     = __nv_bfloat162{
        __float2bfloat16(v.x - __bfloat162float(hx)), __float2bfloat16(v.y - __bfloat162float(hy))};
    *(__nv_bfloat162*)(g_xr_lo + o + 2) = __nv_bfloat162{
        __float2bfloat16(v.z - __bfloat162float(hz)), __float2bfloat16(v.w - __bfloat162float(hw))};
}

// ---------------------------------------------------------------------------
// LSTM wavefront u: layer 0 does t=u, layer 1 does t=u-1.
// grid (16, 8, 2) = 256 CTAs, 256 threads, 2 CTAs/SM.
// CTA tile 128(m) x 64(n'), K=512, BK=32, 3-stage cp.async pipeline.
// Warp layout 4m x 2n (warp tile 32x32). bf16 hi/lo 3-product mma.sync.
// ---------------------------------------------------------------------------
__global__ __launch_bounds__(256, 2) void lstm_step_mma(int u) {
    const int layer = blockIdx.z;
    const int t = u - layer;
    if (t < 0 || t >= T_SZ) return;

    extern __shared__ char smem[];
    const uint32_t sb = smem_u32(smem);
    const int tid  = threadIdx.x;
    const int lane = tid & 31;
    const int wid  = tid >> 5;
    const int wm   = wid & 3;        // 4 m-warps (32 rows each)
    const int wn   = wid >> 2;       // 2 n-warps (32 cols each)
    const int n0 = blockIdx.x * 64;
    const int m0 = blockIdx.y * 128;

    // operand sources
    const __nv_bfloat16 *xh, *xl, *hh, *hl;
    if (layer == 0) {
        xh = g_xr_hi + (size_t)t * BH;  xl = g_xr_lo + (size_t)t * BH;
        if (t == 0) { hh = g_zero_bf; hl = g_zero_bf; }
        else { hh = g_hs0_hi + (size_t)(t - 1) * BH; hl = g_hs0_lo + (size_t)(t - 1) * BH; }
    } else {
        xh = g_hs0_hi + (size_t)t * BH; xl = g_hs0_lo + (size_t)t * BH;
        if (t == 0) { hh = g_zero_bf; hl = g_zero_bf; }
        else { hh = g_h1_hi[(t - 1) & 1]; hl = g_h1_lo[(t - 1) & 1]; }
    }
    __nv_bfloat16* out_hi = (layer == 0) ? (g_hs0_hi + (size_t)t * BH) : g_h1_hi[t & 1];
    __nv_bfloat16* out_lo = (layer == 0) ? (g_hs0_lo + (size_t)t * BH) : g_h1_lo[t & 1];
    float* cst = g_c[layer];
    const __nv_bfloat16* WH = g_Wp_hi[layer];
    const __nv_bfloat16* WL = g_Wp_lo[layer];

    // ---- chunk loader ----
    auto load_chunk = [&](int ck) {
        const int buf = ck % 3;
        const int kk = ck * 32;
        const __nv_bfloat16* ah = (kk < H_SZ) ? xh : hh;
        const __nv_bfloat16* al = (kk < H_SZ) ? xl : hl;
        const int koff = kk & (H_SZ - 1);
        // A: 128 rows x 32 cols, 512 x 16B chunks -> 2 per thread (hi & lo each)
        #pragma unroll
        for (int i = 0; i < 2; i++) {
            int idx = tid + i * 256;
            int row = idx >> 2, c16 = idx & 3;
            size_t ge = (size_t)(m0 + row) * H_SZ + koff + c16 * 8;
            uint32_t so = sb + OFF_AHI(buf) + row * 80 + c16 * 16;
            cpasync16(so, ah + ge);
            cpasync16(so + A_TILE_B, al + ge);
        }
        // B: 64 rows x 32 cols, 256 x 16B chunks -> 1 per thread (hi & lo each)
        {
            int row = tid >> 2, c16 = tid & 3;
            size_t ge = (size_t)(n0 + row) * KC + kk + c16 * 8;
            uint32_t so = sb + OFF_BHI(buf) + row * 80 + c16 * 16;
            cpasync16(so, WH + ge);
            cpasync16(so + B_TILE_B, WL + ge);
        }
        CP_COMMIT();
    };

    float acc[2][4][4];
    #pragma unroll
    for (int a = 0; a < 2; a++)
        #pragma unroll
        for (int b = 0; b < 4; b++)
            #pragma unroll
            for (int q = 0; q < 4; q++) acc[a][b][q] = 0.f;

    load_chunk(0);
    load_chunk(1);

    const uint32_t a_lane = (uint32_t)((lane & 15) * 80 + ((lane >> 4) << 4));
    const uint32_t b_lane = (uint32_t)(((lane & 7) + ((lane >> 4) & 1) * 8) * 80 +
                                       ((lane >> 3) & 1) * 16);

    #pragma unroll 1
    for (int ck = 0; ck < 16; ck++) {
        const int buf = ck % 3;
        if (ck < 15) { CP_WAIT1(); } else { CP_WAIT0(); }
        __syncthreads();                  // all warps done with chunk ck-1
        if (ck < 14) load_chunk(ck + 2);  // safe: buffer (ck+2)%3 == (ck-1)%3

        #pragma unroll
        for (int ks = 0; ks < 2; ks++) {
            const uint32_t kso = (uint32_t)(ks * 32);
            uint32_t bhf[4][2], blf[4][2];
            #pragma unroll
            for (int blk = 0; blk < 2; blk++) {
                uint32_t ad = sb + OFF_BHI(buf) + (wn * 32 + blk * 16) * 80 + kso + b_lane;
                LDSM4(bhf[blk * 2][0], bhf[blk * 2][1], bhf[blk * 2 + 1][0], bhf[blk * 2 + 1][1], ad);
                LDSM4(blf[blk * 2][0], blf[blk * 2][1], blf[blk * 2 + 1][0], blf[blk * 2 + 1][1],
                      ad + B_TILE_B);
            }
            uint32_t af[2][4];
            #pragma unroll
            for (int mf = 0; mf < 2; mf++) {
                uint32_t ad = sb + OFF_AHI(buf) + (wm * 32 + mf * 16) * 80 + kso + a_lane;
                LDSM4(af[mf][0], af[mf][1], af[mf][2], af[mf][3], ad);
            }
            #pragma unroll
            for (int mf = 0; mf < 2; mf++)
                #pragma unroll
                for (int nf = 0; nf < 4; nf++) {
                    MMA16816(acc[mf][nf], af[mf], bhf[nf]);
                    MMA16816(acc[mf][nf], af[mf], blf[nf]);
                }
            #pragma unroll
            for (int mf = 0; mf < 2; mf++) {
                uint32_t ad = sb + OFF_ALO(buf) + (wm * 32 + mf * 16) * 80 + kso + a_lane;
                LDSM4(af[mf][0], af[mf][1], af[mf][2], af[mf][3], ad);
            }
            #pragma unroll
            for (int mf = 0; mf < 2; mf++)
                #pragma unroll
                for (int nf = 0; nf < 4; nf++)
                    MMA16816(acc[mf][nf], af[mf], bhf[nf]);
        }
    }
    __syncthreads();   // buffers dead; gates staging may alias them

    // ---- stage gates to SMEM: [128][68] fp32 ----
    float* gates = (float*)smem;
    #pragma unroll
    for (int mf = 0; mf < 2; mf++)
        #pragma unroll
        for (int nf = 0; nf < 4; nf++) {
            int r = wm * 32 + mf * 16 + (lane >> 2);
            int cc = wn * 32 + nf * 8 + (lane & 3) * 2;
            gates[r * 68 + cc]           = acc[mf][nf][0];
            gates[r * 68 + cc + 1]       = acc[mf][nf][1];
            gates[(r + 8) * 68 + cc]     = acc[mf][nf][2];
            gates[(r + 8) * 68 + cc + 1] = acc[mf][nf][3];
        }
    __syncthreads();

    // ---- fused LSTM pointwise: 128 rows x 16 hidden units per CTA ----
    const int j0 = n0 >> 2;
    const float* bp = g_biasP[layer] + n0;
    #pragma unroll
    for (int i = 0; i < 8; i++) {
        int e = i * 256 + tid;
        int row = e >> 4, j = e & 15;
        float4 bq = *(const float4*)(bp + 4 * j);
        float4 gq = *(const float4*)(gates + row * 68 + 4 * j);
        float gi = gq.x + bq.x, gf = gq.y + bq.y, gg = gq.z + bq.z, go = gq.w + bq.w;
        size_t ci = (size_t)(m0 + row) * H_SZ + j0 + j;
        float cold = cst[ci];
        float cn = fsigm(gf) * cold + fsigm(gi) * ftanh(gg);
        float hn = fsigm(go) * ftanh(cn);
        cst[ci] = cn;
        __nv_bfloat16 hb = __float2bfloat16(hn);
        out_hi[ci] = hb;
        out_lo[ci] = __float2bfloat16(hn - __bfloat162float(hb));
    }
}

// ---------------------------------------------------------------------------
// FC head
// ---------------------------------------------------------------------------
__global__ __launch_bounds__(128) void fc_head(const float* __restrict__ fc1w,
                                               const float* __restrict__ fc1b,
                                               const float* __restrict__ fc2w,
                                               const float* __restrict__ fc2b,
                                               float* __restrict__ out) {
    __shared__ float sh[H_SZ];
    __shared__ float red[128];
    const int b = blockIdx.x, t = threadIdx.x;
    const __nv_bfloat16* hh = g_h1_hi[(T_SZ - 1) & 1];
    const __nv_bfloat16* hl = g_h1_lo[(T_SZ - 1) & 1];
    sh[t]       = __bfloat162float(hh[b * H_SZ + t])       + __bfloat162float(hl[b * H_SZ + t]);
    sh[t + 128] = __bfloat162float(hh[b * H_SZ + t + 128]) + __bfloat162float(hl[b * H_SZ + t + 128]);
    __syncthreads();
    float acc = 0.f;
    const float* wr = fc1w + t * H_SZ;
    #pragma unroll 8
    for (int k = 0; k < H_SZ; k++) acc += sh[k] * wr[k];
    acc += fc1b[t];
    acc = fmaxf(acc, 0.f) * fc2w[t];
    red[t] = acc;
    __syncthreads();
    for (int s = 64; s > 0; s >>= 1) {
        if (t < s) red[t] += red[t + s];
        __syncthreads();
    }
    if (t == 0) out[b] = 1.f / (1.f + expf(-(red[0] + fc2b[0])));
}

// ---------------------------------------------------------------------------
// Launch
// ---------------------------------------------------------------------------
extern "C" void kernel_launch(void* const* d_in, const int* in_sizes, int n_in,
                              void* d_out, int out_size) {
    const float* x    = (const float*)d_in[0];
    const float* wih0 = (const float*)d_in[1];
    const float* whh0 = (const float*)d_in[2];
    const float* bih0 = (const float*)d_in[3];
    const float* bhh0 = (const float*)d_in[4];
    const float* wih1 = (const float*)d_in[5];
    const float* whh1 = (const float*)d_in[6];
    const float* bih1 = (const float*)d_in[7];
    const float* bhh1 = (const float*)d_in[8];
    const float* fc1w = (const float*)d_in[9];
    const float* fc1b = (const float*)d_in[10];
    const float* fc2w = (const float*)d_in[11];
    const float* fc2b = (const float*)d_in[12];
    float* out = (float*)d_out;

    cudaFuncSetAttribute(lstm_step_mma, cudaFuncAttributeMaxDynamicSharedMemorySize, SMEM_TOTAL);

    prep_weights<<<(2 * NG * KC + 255) / 256, 256>>>(wih0, whh0, wih1, whh1);
    prep_misc<<<(2 * BH + 2 * NG + 255) / 256, 256>>>(bih0, bhh0, bih1, bhh1);
    relu_split<<<(T_SZ * B_SZ * (H_SZ / 4) + 255) / 256, 256>>>(x);

    dim3 grid(NG / 64, B_SZ / 128, 2);   // (16, 8, 2) = 256 CTAs
    for (int u = 0; u <= T_SZ; u++) lstm_step_mma<<<grid, 256, SMEM_TOTAL>>>(u);

    fc_head<<<B_SZ, 128>>>(fc1w, fc1b, fc2w, fc2b, out);
}

// round 7
// speedup vs baseline: 4.4611x; 1.1005x over previous
#include <cuda_runtime.h>
#include <cuda_bf16.h>
#include <cstdint>
#include <math.h>

#define B_SZ 1024
#define T_SZ 128
#define H_SZ 256
#define NG   1024            // 4*H
#define KC   512             // combined K (x | h)
#define BH   (B_SZ * H_SZ)

// ---------------------------------------------------------------------------
// Static device scratch (no cudaMalloc anywhere)
// ---------------------------------------------------------------------------
__device__ __align__(16) __nv_bfloat16 g_xr_hi [T_SZ * BH];
__device__ __align__(16) __nv_bfloat16 g_xr_lo [T_SZ * BH];
__device__ __align__(16) __nv_bfloat16 g_hs0_hi[T_SZ * BH];
__device__ __align__(16) __nv_bfloat16 g_hs0_lo[T_SZ * BH];
__device__ __align__(16) __nv_bfloat16 g_h1_hi [2][BH];
__device__ __align__(16) __nv_bfloat16 g_h1_lo [2][BH];
__device__ __align__(16) __nv_bfloat16 g_zero_bf[BH];      // never written -> zero
__device__ __align__(16) float         g_c[2][BH];
__device__ __align__(16) __nv_bfloat16 g_Wp_hi[2][NG * KC]; // [n'][K], n'=4j+g
__device__ __align__(16) __nv_bfloat16 g_Wp_lo[2][NG * KC];
__device__ __align__(16) float         g_biasP[2][NG];

// ---------------------------------------------------------------------------
// PTX helpers (plain sm_100: cp.async + ldmatrix + mma.sync)
// ---------------------------------------------------------------------------
__device__ __forceinline__ uint32_t smem_u32(const void* p) {
    uint32_t a;
    asm("{ .reg .u64 t; cvta.to.shared.u64 t, %1; cvt.u32.u64 %0, t; }" : "=r"(a) : "l"(p));
    return a;
}
__device__ __forceinline__ void cpasync16(uint32_t s, const void* g) {
    asm volatile("cp.async.cg.shared.global [%0], [%1], 16;" :: "r"(s), "l"(g));
}
#define CP_COMMIT() asm volatile("cp.async.commit_group;" ::: "memory")
#define CP_WAIT1()  asm volatile("cp.async.wait_group 1;" ::: "memory")
#define CP_WAIT0()  asm volatile("cp.async.wait_group 0;" ::: "memory")

#define LDSM4(r0, r1, r2, r3, addr) asm volatile( \
    "ldmatrix.sync.aligned.m8n8.x4.shared.b16 {%0,%1,%2,%3}, [%4];" \
    : "=r"(r0), "=r"(r1), "=r"(r2), "=r"(r3) : "r"(addr))

#define MMA16816(d, a, b) asm volatile( \
    "mma.sync.aligned.m16n8k16.row.col.f32.bf16.bf16.f32 " \
    "{%0,%1,%2,%3}, {%4,%5,%6,%7}, {%8,%9}, {%0,%1,%2,%3};" \
    : "+f"((d)[0]), "+f"((d)[1]), "+f"((d)[2]), "+f"((d)[3]) \
    : "r"((a)[0]), "r"((a)[1]), "r"((a)[2]), "r"((a)[3]), "r"((b)[0]), "r"((b)[1]))

// SMEM: 2 pipeline stages. Per chunk (BK=64):
//   tiles are 128 rows x 64 bf16 (128B) padded to 144B pitch -> 18432B each
//   stage = {Ahi, Alo, Bhi, Blo} = 73728B
#define PITCH    144
#define TILE_B   18432                 // 128*144
#define BUF_SZ   (4 * TILE_B)          // 73728
#define OFF_AHI(b) ((b) * BUF_SZ)
#define OFF_ALO(b) ((b) * BUF_SZ + TILE_B)
#define OFF_BHI(b) ((b) * BUF_SZ + 2 * TILE_B)
#define SMEM_TOTAL (2 * BUF_SZ)        // 147456; gates [128][132] fp32 aliases

__device__ __forceinline__ float fsigm(float x) {
    x = fminf(fmaxf(x, -30.f), 30.f);
    return __fdividef(1.f, 1.f + __expf(-x));
}
__device__ __forceinline__ float ftanh(float x) {
    x = fminf(fmaxf(x, -15.f), 15.f);
    float e = __expf(2.f * x);
    return (e - 1.f) * __fdividef(1.f, e + 1.f);
}

// ---------------------------------------------------------------------------
// Prep kernels
// ---------------------------------------------------------------------------
__global__ void prep_weights(const float* __restrict__ wih0, const float* __restrict__ whh0,
                             const float* __restrict__ wih1, const float* __restrict__ whh1) {
    int id = blockIdx.x * blockDim.x + threadIdx.x;
    if (id >= 2 * NG * KC) return;
    int layer = id >> 19;
    int rem   = id & ((1 << 19) - 1);
    int np = rem >> 9;
    int k  = rem & 511;
    int j = np >> 2, g = np & 3;
    int n = g * H_SZ + j;
    const float* wih = layer ? wih1 : wih0;
    const float* whh = layer ? whh1 : whh0;
    float w = (k < H_SZ) ? wih[n * H_SZ + k] : whh[n * H_SZ + (k - H_SZ)];
    __nv_bfloat16 hi = __float2bfloat16(w);
    __nv_bfloat16 lo = __float2bfloat16(w - __bfloat162float(hi));
    g_Wp_hi[layer][np * KC + k] = hi;
    g_Wp_lo[layer][np * KC + k] = lo;
}

__global__ void prep_misc(const float* __restrict__ bih0, const float* __restrict__ bhh0,
                          const float* __restrict__ bih1, const float* __restrict__ bhh1) {
    int id = blockIdx.x * blockDim.x + threadIdx.x;
    if (id < BH)          g_c[0][id] = 0.0f;
    else if (id < 2 * BH) g_c[1][id - BH] = 0.0f;
    else if (id < 2 * BH + 2 * NG) {
        int r = id - 2 * BH;
        int layer = r >> 10;
        int np = r & 1023;
        int j = np >> 2, g = np & 3;
        int n = g * H_SZ + j;
        const float* bi = layer ? bih1 : bih0;
        const float* bh = layer ? bhh1 : bhh0;
        g_biasP[layer][np] = bi[n] + bh[n];
    }
}

// relu + [B,T,H]->[T,B,H] + bf16 hi/lo split
__global__ void relu_split(const float* __restrict__ x) {
    int id = blockIdx.x * blockDim.x + threadIdx.x;
    if (id >= T_SZ * B_SZ * (H_SZ / 4)) return;
    int t   = id / (B_SZ * (H_SZ / 4));
    int rem = id % (B_SZ * (H_SZ / 4));
    int b   = rem / (H_SZ / 4);
    int e4  = rem % (H_SZ / 4);
    float4 v = *(const float4*)(x + (size_t)b * T_SZ * H_SZ + t * H_SZ + e4 * 4);
    v.x = fmaxf(v.x, 0.f); v.y = fmaxf(v.y, 0.f);
    v.z = fmaxf(v.z, 0.f); v.w = fmaxf(v.w, 0.f);
    size_t o = (size_t)t * BH + b * H_SZ + e4 * 4;
    __nv_bfloat16 hx = __float2bfloat16(v.x), hy = __float2bfloat16(v.y);
    __nv_bfloat16 hz = __float2bfloat16(v.z), hw = __float2bfloat16(v.w);
    *(__nv_bfloat162*)(g_xr_hi + o)     = __nv_bfloat162{hx, hy};
    *(__nv_bfloat162*)(g_xr_hi + o + 2) = __nv_bfloat162{hz, hw};
    *(__nv_bfloat162*)(g_xr_lo + o)     = __nv_bfloat162{
        __float2bfloat16(v.x - __bfloat162float(hx)), __float2bfloat16(v.y - __bfloat162float(hy))};
    *(__nv_bfloat162*)(g_xr_lo + o + 2) = __nv_bfloat162{
        __float2bfloat16(v.z - __bfloat162float(hz)), __float2bfloat16(v.w - __bfloat162float(hw))};
}

// ---------------------------------------------------------------------------
// LSTM wavefront u: layer 0 does t=u, layer 1 does t=u-1.
// grid (8, 8, 2) = 128 CTAs, 512 threads (16 warps/SM guaranteed).
// CTA tile 128(m) x 128(n'), K=512, BK=64, 2-stage cp.async pipeline.
// Warp layout 4m x 4n (warp tile 32x32). bf16 hi/lo 3-product mma.sync.
// ---------------------------------------------------------------------------
__global__ __launch_bounds__(512, 1) void lstm_step_mma(int u) {
    const int layer = blockIdx.z;
    const int t = u - layer;
    if (t < 0 || t >= T_SZ) return;

    extern __shared__ char smem[];
    const uint32_t sb = smem_u32(smem);
    const int tid  = threadIdx.x;
    const int lane = tid & 31;
    const int wid  = tid >> 5;
    const int wm   = wid & 3;        // 4 m-warps (32 rows each)
    const int wn   = wid >> 2;       // 4 n-warps (32 cols each)
    const int n0 = blockIdx.x * 128;
    const int m0 = blockIdx.y * 128;

    // operand sources
    const __nv_bfloat16 *xh, *xl, *hh, *hl;
    if (layer == 0) {
        xh = g_xr_hi + (size_t)t * BH;  xl = g_xr_lo + (size_t)t * BH;
        if (t == 0) { hh = g_zero_bf; hl = g_zero_bf; }
        else { hh = g_hs0_hi + (size_t)(t - 1) * BH; hl = g_hs0_lo + (size_t)(t - 1) * BH; }
    } else {
        xh = g_hs0_hi + (size_t)t * BH; xl = g_hs0_lo + (size_t)t * BH;
        if (t == 0) { hh = g_zero_bf; hl = g_zero_bf; }
        else { hh = g_h1_hi[(t - 1) & 1]; hl = g_h1_lo[(t - 1) & 1]; }
    }
    __nv_bfloat16* out_hi = (layer == 0) ? (g_hs0_hi + (size_t)t * BH) : g_h1_hi[t & 1];
    __nv_bfloat16* out_lo = (layer == 0) ? (g_hs0_lo + (size_t)t * BH) : g_h1_lo[t & 1];
    float* cst = g_c[layer];
    const __nv_bfloat16* WH = g_Wp_hi[layer];
    const __nv_bfloat16* WL = g_Wp_lo[layer];

    // ---- chunk loader: BK=64. A/B tiles 128 rows x 64 bf16 (8x16B per row) ----
    auto load_chunk = [&](int ck) {
        const int buf = ck & 1;
        const int kk = ck * 64;
        const __nv_bfloat16* ah = (kk < H_SZ) ? xh : hh;
        const __nv_bfloat16* al = (kk < H_SZ) ? xl : hl;
        const int koff = kk & (H_SZ - 1);
        #pragma unroll
        for (int i = 0; i < 2; i++) {
            int idx = tid + i * 512;              // 0..1023
            int row = idx >> 3, c16 = idx & 7;
            size_t ga = (size_t)(m0 + row) * H_SZ + koff + c16 * 8;
            uint32_t so = sb + OFF_AHI(buf) + row * PITCH + c16 * 16;
            cpasync16(so, ah + ga);
            cpasync16(so + TILE_B, al + ga);
            size_t gb = (size_t)(n0 + row) * KC + kk + c16 * 8;
            uint32_t sob = sb + OFF_BHI(buf) + row * PITCH + c16 * 16;
            cpasync16(sob, WH + gb);
            cpasync16(sob + TILE_B, WL + gb);
        }
        CP_COMMIT();
    };

    float acc[2][4][4];
    #pragma unroll
    for (int a = 0; a < 2; a++)
        #pragma unroll
        for (int b = 0; b < 4; b++)
            #pragma unroll
            for (int q = 0; q < 4; q++) acc[a][b][q] = 0.f;

    load_chunk(0);

    const uint32_t a_lane = (uint32_t)((lane & 15) * PITCH + ((lane >> 4) << 4));
    const uint32_t b_lane = (uint32_t)(((lane & 7) + ((lane >> 4) & 1) * 8) * PITCH +
                                       ((lane >> 3) & 1) * 16);

    #pragma unroll 1
    for (int ck = 0; ck < 8; ck++) {
        const int buf = ck & 1;
        if (ck < 7) load_chunk(ck + 1);
        if (ck < 7) { CP_WAIT1(); } else { CP_WAIT0(); }
        __syncthreads();

        #pragma unroll
        for (int ks = 0; ks < 4; ks++) {
            const uint32_t kso = (uint32_t)(ks * 32);
            uint32_t bhf[4][2], blf[4][2];
            #pragma unroll
            for (int blk = 0; blk < 2; blk++) {
                uint32_t ad = sb + OFF_BHI(buf) + (wn * 32 + blk * 16) * PITCH + kso + b_lane;
                LDSM4(bhf[blk * 2][0], bhf[blk * 2][1], bhf[blk * 2 + 1][0], bhf[blk * 2 + 1][1], ad);
                LDSM4(blf[blk * 2][0], blf[blk * 2][1], blf[blk * 2 + 1][0], blf[blk * 2 + 1][1],
                      ad + TILE_B);
            }
            uint32_t af[2][4];
            #pragma unroll
            for (int mf = 0; mf < 2; mf++) {
                uint32_t ad = sb + OFF_AHI(buf) + (wm * 32 + mf * 16) * PITCH + kso + a_lane;
                LDSM4(af[mf][0], af[mf][1], af[mf][2], af[mf][3], ad);
            }
            #pragma unroll
            for (int mf = 0; mf < 2; mf++)
                #pragma unroll
                for (int nf = 0; nf < 4; nf++) {
                    MMA16816(acc[mf][nf], af[mf], bhf[nf]);
                    MMA16816(acc[mf][nf], af[mf], blf[nf]);
                }
            #pragma unroll
            for (int mf = 0; mf < 2; mf++) {
                uint32_t ad = sb + OFF_ALO(buf) + (wm * 32 + mf * 16) * PITCH + kso + a_lane;
                LDSM4(af[mf][0], af[mf][1], af[mf][2], af[mf][3], ad);
            }
            #pragma unroll
            for (int mf = 0; mf < 2; mf++)
                #pragma unroll
                for (int nf = 0; nf < 4; nf++)
                    MMA16816(acc[mf][nf], af[mf], bhf[nf]);
        }
        __syncthreads();
    }

    // ---- stage gates to SMEM: [128][132] fp32 (aliases dead tile buffers) ----
    float* gates = (float*)smem;
    #pragma unroll
    for (int mf = 0; mf < 2; mf++)
        #pragma unroll
        for (int nf = 0; nf < 4; nf++) {
            int r = wm * 32 + mf * 16 + (lane >> 2);
            int cc = wn * 32 + nf * 8 + (lane & 3) * 2;
            gates[r * 132 + cc]           = acc[mf][nf][0];
            gates[r * 132 + cc + 1]       = acc[mf][nf][1];
            gates[(r + 8) * 132 + cc]     = acc[mf][nf][2];
            gates[(r + 8) * 132 + cc + 1] = acc[mf][nf][3];
        }
    __syncthreads();

    // ---- fused LSTM pointwise: 128 rows x 32 hidden units per CTA ----
    const int j0 = n0 >> 2;
    const float* bp = g_biasP[layer] + n0;
    #pragma unroll
    for (int i = 0; i < 8; i++) {
        int e = i * 512 + tid;
        int row = e >> 5, j = e & 31;
        float4 bq = *(const float4*)(bp + 4 * j);
        float4 gq = *(const float4*)(gates + row * 132 + 4 * j);
        float gi = gq.x + bq.x, gf = gq.y + bq.y, gg = gq.z + bq.z, go = gq.w + bq.w;
        size_t ci = (size_t)(m0 + row) * H_SZ + j0 + j;
        float cold = cst[ci];
        float cn = fsigm(gf) * cold + fsigm(gi) * ftanh(gg);
        float hn = fsigm(go) * ftanh(cn);
        cst[ci] = cn;
        __nv_bfloat16 hb = __float2bfloat16(hn);
        out_hi[ci] = hb;
        out_lo[ci] = __float2bfloat16(hn - __bfloat162float(hb));
    }
}

// ---------------------------------------------------------------------------
// FC head
// ---------------------------------------------------------------------------
__global__ __launch_bounds__(128) void fc_head(const float* __restrict__ fc1w,
                                               const float* __restrict__ fc1b,
                                               const float* __restrict__ fc2w,
                                               const float* __restrict__ fc2b,
                                               float* __restrict__ out) {
    __shared__ float sh[H_SZ];
    __shared__ float red[128];
    const int b = blockIdx.x, t = threadIdx.x;
    const __nv_bfloat16* hh = g_h1_hi[(T_SZ - 1) & 1];
    const __nv_bfloat16* hl = g_h1_lo[(T_SZ - 1) & 1];
    sh[t]       = __bfloat162float(hh[b * H_SZ + t])       + __bfloat162float(hl[b * H_SZ + t]);
    sh[t + 128] = __bfloat162float(hh[b * H_SZ + t + 128]) + __bfloat162float(hl[b * H_SZ + t + 128]);
    __syncthreads();
    float acc = 0.f;
    const float* wr = fc1w + t * H_SZ;
    #pragma unroll 8
    for (int k = 0; k < H_SZ; k++) acc += sh[k] * wr[k];
    acc += fc1b[t];
    acc = fmaxf(acc, 0.f) * fc2w[t];
    red[t] = acc;
    __syncthreads();
    for (int s = 64; s > 0; s >>= 1) {
        if (t < s) red[t] += red[t + s];
        __syncthreads();
    }
    if (t == 0) out[b] = 1.f / (1.f + expf(-(red[0] + fc2b[0])));
}

// ---------------------------------------------------------------------------
// Launch
// ---------------------------------------------------------------------------
extern "C" void kernel_launch(void* const* d_in, const int* in_sizes, int n_in,
                              void* d_out, int out_size) {
    const float* x    = (const float*)d_in[0];
    const float* wih0 = (const float*)d_in[1];
    const float* whh0 = (const float*)d_in[2];
    const float* bih0 = (const float*)d_in[3];
    const float* bhh0 = (const float*)d_in[4];
    const float* wih1 = (const float*)d_in[5];
    const float* whh1 = (const float*)d_in[6];
    const float* bih1 = (const float*)d_in[7];
    const float* bhh1 = (const float*)d_in[8];
    const float* fc1w = (const float*)d_in[9];
    const float* fc1b = (const float*)d_in[10];
    const float* fc2w = (const float*)d_in[11];
    const float* fc2b = (const float*)d_in[12];
    float* out = (float*)d_out;

    cudaFuncSetAttribute(lstm_step_mma, cudaFuncAttributeMaxDynamicSharedMemorySize, SMEM_TOTAL);

    prep_weights<<<(2 * NG * KC + 255) / 256, 256>>>(wih0, whh0, wih1, whh1);
    prep_misc<<<(2 * BH + 2 * NG + 255) / 256, 256>>>(bih0, bhh0, bih1, bhh1);
    relu_split<<<(T_SZ * B_SZ * (H_SZ / 4) + 255) / 256, 256>>>(x);

    dim3 grid(NG / 128, B_SZ / 128, 2);   // (8, 8, 2) = 128 CTAs x 512 threads
    for (int u = 0; u <= T_SZ; u++) lstm_step_mma<<<grid, 512, SMEM_TOTAL>>>(u);

    fc_head<<<B_SZ, 128>>>(fc1w, fc1b, fc2w, fc2b, out);
}

// round 9
// speedup vs baseline: 4.4754x; 1.0032x over previous
#include <cuda_runtime.h>
#include <cuda_bf16.h>
#include <cstdint>
#include <math.h>

#define B_SZ 1024
#define T_SZ 128
#define H_SZ 256
#define NG   1024            // 4*H
#define KC   512             // combined K (x | h)
#define BH   (B_SZ * H_SZ)

// ---------------------------------------------------------------------------
// Static device scratch (no cudaMalloc anywhere)
// ---------------------------------------------------------------------------
__device__ __align__(16) __nv_bfloat16 g_xr_hi [T_SZ * BH];
__device__ __align__(16) __nv_bfloat16 g_xr_lo [T_SZ * BH];
__device__ __align__(16) __nv_bfloat16 g_hs0_hi[T_SZ * BH];
__device__ __align__(16) __nv_bfloat16 g_hs0_lo[T_SZ * BH];
__device__ __align__(16) __nv_bfloat16 g_h1_hi [2][BH];
__device__ __align__(16) __nv_bfloat16 g_h1_lo [2][BH];
__device__ __align__(16) __nv_bfloat16 g_zero_bf[BH];      // never written -> zero
__device__ __align__(16) float         g_c[2][BH];
__device__ __align__(16) __nv_bfloat16 g_Wp_hi[2][NG * KC]; // [n'][K], n'=4j+g
__device__ __align__(16) __nv_bfloat16 g_Wp_lo[2][NG * KC];
__device__ __align__(16) float         g_biasP[2][NG];

// ---------------------------------------------------------------------------
// PTX helpers (plain sm_100: cp.async + ldmatrix + mma.sync)
// ---------------------------------------------------------------------------
__device__ __forceinline__ uint32_t smem_u32(const void* p) {
    uint32_t a;
    asm("{ .reg .u64 t; cvta.to.shared.u64 t, %1; cvt.u32.u64 %0, t; }" : "=r"(a) : "l"(p));
    return a;
}
__device__ __forceinline__ void cpasync16(uint32_t s, const void* g) {
    asm volatile("cp.async.cg.shared.global [%0], [%1], 16;" :: "r"(s), "l"(g));
}
#define CP_COMMIT() asm volatile("cp.async.commit_group;" ::: "memory")
#define CP_WAIT1()  asm volatile("cp.async.wait_group 1;" ::: "memory")
#define CP_WAIT0()  asm volatile("cp.async.wait_group 0;" ::: "memory")

#define LDSM4(r0, r1, r2, r3, addr) asm volatile( \
    "ldmatrix.sync.aligned.m8n8.x4.shared.b16 {%0,%1,%2,%3}, [%4];" \
    : "=r"(r0), "=r"(r1), "=r"(r2), "=r"(r3) : "r"(addr))

#define MMA16816(d, a, b) asm volatile( \
    "mma.sync.aligned.m16n8k16.row.col.f32.bf16.bf16.f32 " \
    "{%0,%1,%2,%3}, {%4,%5,%6,%7}, {%8,%9}, {%0,%1,%2,%3};" \
    : "+f"((d)[0]), "+f"((d)[1]), "+f"((d)[2]), "+f"((d)[3]) \
    : "r"((a)[0]), "r"((a)[1]), "r"((a)[2]), "r"((a)[3]), "r"((b)[0]), "r"((b)[1]))

// SMEM: 2 pipeline stages (PROVEN R7 layout). Per chunk (BK=64):
//   tiles 128 rows x 64 bf16 (128B) padded to 144B pitch -> 18432B each
//   stage = {Ahi, Alo, Bhi, Blo} = 73728B
#define PITCH    144
#define TILE_B   18432                 // 128*144
#define BUF_SZ   (4 * TILE_B)          // 73728
#define OFF_AHI(b) ((b) * BUF_SZ)
#define OFF_ALO(b) ((b) * BUF_SZ + TILE_B)
#define OFF_BHI(b) ((b) * BUF_SZ + 2 * TILE_B)
#define SMEM_TOTAL (2 * BUF_SZ)        // 147456; gates [128][132] fp32 aliases

__device__ __forceinline__ float fsigm(float x) {
    x = fminf(fmaxf(x, -30.f), 30.f);
    return __fdividef(1.f, 1.f + __expf(-x));
}
__device__ __forceinline__ float ftanh(float x) {
    x = fminf(fmaxf(x, -15.f), 15.f);
    float e = __expf(2.f * x);
    return (e - 1.f) * __fdividef(1.f, e + 1.f);
}

// ---------------------------------------------------------------------------
// Prep kernels
// ---------------------------------------------------------------------------
__global__ void prep_weights(const float* __restrict__ wih0, const float* __restrict__ whh0,
                             const float* __restrict__ wih1, const float* __restrict__ whh1) {
    int id = blockIdx.x * blockDim.x + threadIdx.x;
    if (id >= 2 * NG * KC) return;
    int layer = id >> 19;
    int rem   = id & ((1 << 19) - 1);
    int np = rem >> 9;
    int k  = rem & 511;
    int j = np >> 2, g = np & 3;
    int n = g * H_SZ + j;
    const float* wih = layer ? wih1 : wih0;
    const float* whh = layer ? whh1 : whh0;
    float w = (k < H_SZ) ? wih[n * H_SZ + k] : whh[n * H_SZ + (k - H_SZ)];
    __nv_bfloat16 hi = __float2bfloat16(w);
    __nv_bfloat16 lo = __float2bfloat16(w - __bfloat162float(hi));
    g_Wp_hi[layer][np * KC + k] = hi;
    g_Wp_lo[layer][np * KC + k] = lo;
}

__global__ void prep_misc(const float* __restrict__ bih0, const float* __restrict__ bhh0,
                          const float* __restrict__ bih1, const float* __restrict__ bhh1) {
    int id = blockIdx.x * blockDim.x + threadIdx.x;
    if (id < BH)          g_c[0][id] = 0.0f;
    else if (id < 2 * BH) g_c[1][id - BH] = 0.0f;
    else if (id < 2 * BH + 2 * NG) {
        int r = id - 2 * BH;
        int layer = r >> 10;
        int np = r & 1023;
        int j = np >> 2, g = np & 3;
        int n = g * H_SZ + j;
        const float* bi = layer ? bih1 : bih0;
        const float* bh = layer ? bhh1 : bhh0;
        g_biasP[layer][np] = bi[n] + bh[n];
    }
}

// relu + [B,T,H]->[T,B,H] + bf16 hi/lo split
__global__ void relu_split(const float* __restrict__ x) {
    int id = blockIdx.x * blockDim.x + threadIdx.x;
    if (id >= T_SZ * B_SZ * (H_SZ / 4)) return;
    int t   = id / (B_SZ * (H_SZ / 4));
    int rem = id % (B_SZ * (H_SZ / 4));
    int b   = rem / (H_SZ / 4);
    int e4  = rem % (H_SZ / 4);
    float4 v = *(const float4*)(x + (size_t)b * T_SZ * H_SZ + t * H_SZ + e4 * 4);
    v.x = fmaxf(v.x, 0.f); v.y = fmaxf(v.y, 0.f);
    v.z = fmaxf(v.z, 0.f); v.w = fmaxf(v.w, 0.f);
    size_t o = (size_t)t * BH + b * H_SZ + e4 * 4;
    __nv_bfloat16 hx = __float2bfloat16(v.x), hy = __float2bfloat16(v.y);
    __nv_bfloat16 hz = __float2bfloat16(v.z), hw = __float2bfloat16(v.w);
    *(__nv_bfloat162*)(g_xr_hi + o)     = __nv_bfloat162{hx, hy};
    *(__nv_bfloat162*)(g_xr_hi + o + 2) = __nv_bfloat162{hz, hw};
    *(__nv_bfloat162*)(g_xr_lo + o)     = __nv_bfloat162{
        __float2bfloat16(v.x - __bfloat162float(hx)), __float2bfloat16(v.y - __bfloat162float(hy))};
    *(__nv_bfloat162*)(g_xr_lo + o + 2) = __nv_bfloat162{
        __float2bfloat16(v.z - __bfloat162float(hz)), __float2bfloat16(v.w - __bfloat162float(hw))};
}

// ---------------------------------------------------------------------------
// LSTM wavefront u: layer 0 does t=u, layer 1 does t=u-1.
// grid (8, 8, 2) = 128 CTAs, 512 threads. CTA tile 128x128, K=512, BK=64.
// 2-stage cp.async pipeline (R7-proven). Warp layout 4m x 4n (32x32 tiles).
// NEW vs R7: pass-separated MMA ordering (same-acc reuse distance 8) and
// A-lo LDSM issued between passes so its latency hides under 8 MMAs.
// ---------------------------------------------------------------------------
__global__ __launch_bounds__(512, 1) void lstm_step_mma(int u) {
    const int layer = blockIdx.z;
    const int t = u - layer;
    if (t < 0 || t >= T_SZ) return;

    extern __shared__ char smem[];
    const uint32_t sb = smem_u32(smem);
    const int tid  = threadIdx.x;
    const int lane = tid & 31;
    const int wid  = tid >> 5;
    const int wm   = wid & 3;        // 4 m-warps (32 rows each)
    const int wn   = wid >> 2;       // 4 n-warps (32 cols each)
    const int n0 = blockIdx.x * 128;
    const int m0 = blockIdx.y * 128;

    // operand sources
    const __nv_bfloat16 *xh, *xl, *hh, *hl;
    if (layer == 0) {
        xh = g_xr_hi + (size_t)t * BH;  xl = g_xr_lo + (size_t)t * BH;
        if (t == 0) { hh = g_zero_bf; hl = g_zero_bf; }
        else { hh = g_hs0_hi + (size_t)(t - 1) * BH; hl = g_hs0_lo + (size_t)(t - 1) * BH; }
    } else {
        xh = g_hs0_hi + (size_t)t * BH; xl = g_hs0_lo + (size_t)t * BH;
        if (t == 0) { hh = g_zero_bf; hl = g_zero_bf; }
        else { hh = g_h1_hi[(t - 1) & 1]; hl = g_h1_lo[(t - 1) & 1]; }
    }
    __nv_bfloat16* out_hi = (layer == 0) ? (g_hs0_hi + (size_t)t * BH) : g_h1_hi[t & 1];
    __nv_bfloat16* out_lo = (layer == 0) ? (g_hs0_lo + (size_t)t * BH) : g_h1_lo[t & 1];
    float* cst = g_c[layer];
    const __nv_bfloat16* WH = g_Wp_hi[layer];
    const __nv_bfloat16* WL = g_Wp_lo[layer];

    // ---- chunk loader: BK=64, 2 rotating buffers (R7-proven) ----
    auto load_chunk = [&](int ck) {
        const int buf = ck & 1;
        const int kk = ck * 64;
        const __nv_bfloat16* ah = (kk < H_SZ) ? xh : hh;
        const __nv_bfloat16* al = (kk < H_SZ) ? xl : hl;
        const int koff = kk & (H_SZ - 1);
        #pragma unroll
        for (int i = 0; i < 2; i++) {
            int idx = tid + i * 512;              // 0..1023
            int row = idx >> 3, c16 = idx & 7;
            size_t ga = (size_t)(m0 + row) * H_SZ + koff + c16 * 8;
            uint32_t so = sb + OFF_AHI(buf) + row * PITCH + c16 * 16;
            cpasync16(so, ah + ga);
            cpasync16(so + TILE_B, al + ga);
            size_t gb = (size_t)(n0 + row) * KC + kk + c16 * 8;
            uint32_t sob = sb + OFF_BHI(buf) + row * PITCH + c16 * 16;
            cpasync16(sob, WH + gb);
            cpasync16(sob + TILE_B, WL + gb);
        }
        CP_COMMIT();
    };

    float acc[2][4][4];
    #pragma unroll
    for (int a = 0; a < 2; a++)
        #pragma unroll
        for (int b = 0; b < 4; b++)
            #pragma unroll
            for (int q = 0; q < 4; q++) acc[a][b][q] = 0.f;

    load_chunk(0);

    const uint32_t a_lane = (uint32_t)((lane & 15) * PITCH + ((lane >> 4) << 4));
    const uint32_t b_lane = (uint32_t)(((lane & 7) + ((lane >> 4) & 1) * 8) * PITCH +
                                       ((lane >> 3) & 1) * 16);

    #pragma unroll 1
    for (int ck = 0; ck < 8; ck++) {
        const int buf = ck & 1;
        if (ck < 7) load_chunk(ck + 1);
        if (ck < 7) { CP_WAIT1(); } else { CP_WAIT0(); }
        __syncthreads();

        #pragma unroll
        for (int ks = 0; ks < 4; ks++) {
            const uint32_t kso = (uint32_t)(ks * 32);
            // --- fragment loads: B hi/lo, A hi ---
            uint32_t bhf[4][2], blf[4][2];
            #pragma unroll
            for (int blk = 0; blk < 2; blk++) {
                uint32_t ad = sb + OFF_BHI(buf) + (wn * 32 + blk * 16) * PITCH + kso + b_lane;
                LDSM4(bhf[blk * 2][0], bhf[blk * 2][1], bhf[blk * 2 + 1][0], bhf[blk * 2 + 1][1], ad);
                LDSM4(blf[blk * 2][0], blf[blk * 2][1], blf[blk * 2 + 1][0], blf[blk * 2 + 1][1],
                      ad + TILE_B);
            }
            uint32_t ah_f[2][4];
            #pragma unroll
            for (int mf = 0; mf < 2; mf++) {
                uint32_t ad = sb + OFF_AHI(buf) + (wm * 32 + mf * 16) * PITCH + kso + a_lane;
                LDSM4(ah_f[mf][0], ah_f[mf][1], ah_f[mf][2], ah_f[mf][3], ad);
            }
            // --- pass 1: Ahi x Bhi (8 MMAs, distinct accumulators) ---
            #pragma unroll
            for (int mf = 0; mf < 2; mf++)
                #pragma unroll
                for (int nf = 0; nf < 4; nf++)
                    MMA16816(acc[mf][nf], ah_f[mf], bhf[nf]);
            // --- A-lo LDSM here: latency hidden under pass 2 ---
            uint32_t al_f[2][4];
            #pragma unroll
            for (int mf = 0; mf < 2; mf++) {
                uint32_t ad = sb + OFF_ALO(buf) + (wm * 32 + mf * 16) * PITCH + kso + a_lane;
                LDSM4(al_f[mf][0], al_f[mf][1], al_f[mf][2], al_f[mf][3], ad);
            }
            // --- pass 2: Ahi x Blo (same-acc distance 8 from pass 1) ---
            #pragma unroll
            for (int mf = 0; mf < 2; mf++)
                #pragma unroll
                for (int nf = 0; nf < 4; nf++)
                    MMA16816(acc[mf][nf], ah_f[mf], blf[nf]);
            // --- pass 3: Alo x Bhi ---
            #pragma unroll
            for (int mf = 0; mf < 2; mf++)
                #pragma unroll
                for (int nf = 0; nf < 4; nf++)
                    MMA16816(acc[mf][nf], al_f[mf], bhf[nf]);
        }
        __syncthreads();
    }

    // ---- stage gates to SMEM: [128][132] fp32 (aliases dead tile buffers) ----
    float* gates = (float*)smem;
    #pragma unroll
    for (int mf = 0; mf < 2; mf++)
        #pragma unroll
        for (int nf = 0; nf < 4; nf++) {
            int r = wm * 32 + mf * 16 + (lane >> 2);
            int cc = wn * 32 + nf * 8 + (lane & 3) * 2;
            gates[r * 132 + cc]           = acc[mf][nf][0];
            gates[r * 132 + cc + 1]       = acc[mf][nf][1];
            gates[(r + 8) * 132 + cc]     = acc[mf][nf][2];
            gates[(r + 8) * 132 + cc + 1] = acc[mf][nf][3];
        }
    __syncthreads();

    // ---- fused LSTM pointwise: 128 rows x 32 hidden units per CTA ----
    const int j0 = n0 >> 2;
    const float* bp = g_biasP[layer] + n0;
    #pragma unroll
    for (int i = 0; i < 8; i++) {
        int e = i * 512 + tid;
        int row = e >> 5, j = e & 31;
        float4 bq = *(const float4*)(bp + 4 * j);
        float4 gq = *(const float4*)(gates + row * 132 + 4 * j);
        float gi = gq.x + bq.x, gf = gq.y + bq.y, gg = gq.z + bq.z, go = gq.w + bq.w;
        size_t ci = (size_t)(m0 + row) * H_SZ + j0 + j;
        float cold = cst[ci];
        float cn = fsigm(gf) * cold + fsigm(gi) * ftanh(gg);
        float hn = fsigm(go) * ftanh(cn);
        cst[ci] = cn;
        __nv_bfloat16 hb = __float2bfloat16(hn);
        out_hi[ci] = hb;
        out_lo[ci] = __float2bfloat16(hn - __bfloat162float(hb));
    }
}

// ---------------------------------------------------------------------------
// FC head
// ---------------------------------------------------------------------------
__global__ __launch_bounds__(128) void fc_head(const float* __restrict__ fc1w,
                                               const float* __restrict__ fc1b,
                                               const float* __restrict__ fc2w,
                                               const float* __restrict__ fc2b,
                                               float* __restrict__ out) {
    __shared__ float sh[H_SZ];
    __shared__ float red[128];
    const int b = blockIdx.x, t = threadIdx.x;
    const __nv_bfloat16* hh = g_h1_hi[(T_SZ - 1) & 1];
    const __nv_bfloat16* hl = g_h1_lo[(T_SZ - 1) & 1];
    sh[t]       = __bfloat162float(hh[b * H_SZ + t])       + __bfloat162float(hl[b * H_SZ + t]);
    sh[t + 128] = __bfloat162float(hh[b * H_SZ + t + 128]) + __bfloat162float(hl[b * H_SZ + t + 128]);
    __syncthreads();
    float acc = 0.f;
    const float* wr = fc1w + t * H_SZ;
    #pragma unroll 8
    for (int k = 0; k < H_SZ; k++) acc += sh[k] * wr[k];
    acc += fc1b[t];
    acc = fmaxf(acc, 0.f) * fc2w[t];
    red[t] = acc;
    __syncthreads();
    for (int s = 64; s > 0; s >>= 1) {
        if (t < s) red[t] += red[t + s];
        __syncthreads();
    }
    if (t == 0) out[b] = 1.f / (1.f + expf(-(red[0] + fc2b[0])));
}

// ---------------------------------------------------------------------------
// Launch
// ---------------------------------------------------------------------------
extern "C" void kernel_launch(void* const* d_in, const int* in_sizes, int n_in,
                              void* d_out, int out_size) {
    const float* x    = (const float*)d_in[0];
    const float* wih0 = (const float*)d_in[1];
    const float* whh0 = (const float*)d_in[2];
    const float* bih0 = (const float*)d_in[3];
    const float* bhh0 = (const float*)d_in[4];
    const float* wih1 = (const float*)d_in[5];
    const float* whh1 = (const float*)d_in[6];
    const float* bih1 = (const float*)d_in[7];
    const float* bhh1 = (const float*)d_in[8];
    const float* fc1w = (const float*)d_in[9];
    const float* fc1b = (const float*)d_in[10];
    const float* fc2w = (const float*)d_in[11];
    const float* fc2b = (const float*)d_in[12];
    float* out = (float*)d_out;

    cudaFuncSetAttribute(lstm_step_mma, cudaFuncAttributeMaxDynamicSharedMemorySize, SMEM_TOTAL);

    prep_weights<<<(2 * NG * KC + 255) / 256, 256>>>(wih0, whh0, wih1, whh1);
    prep_misc<<<(2 * BH + 2 * NG + 255) / 256, 256>>>(bih0, bhh0, bih1, bhh1);
    relu_split<<<(T_SZ * B_SZ * (H_SZ / 4) + 255) / 256, 256>>>(x);

    dim3 grid(NG / 128, B_SZ / 128, 2);   // (8, 8, 2) = 128 CTAs x 512 threads
    for (int u = 0; u <= T_SZ; u++) lstm_step_mma<<<grid, 512, SMEM_TOTAL>>>(u);

    fc_head<<<B_SZ, 128>>>(fc1w, fc1b, fc2w, fc2b, out);
}

// round 12
// speedup vs baseline: 5.8081x; 1.2978x over previous
#include <cuda_runtime.h>
#include <cuda_fp16.h>
#include <cstdint>
#include <math.h>

#define B_SZ 1024
#define T_SZ 128
#define H_SZ 256
#define NG   1024            // 4*H
#define KC   512             // combined K (x | h)
#define BH   (B_SZ * H_SZ)

// ---------------------------------------------------------------------------
// Static device scratch (no cudaMalloc anywhere)
// ---------------------------------------------------------------------------
__device__ __align__(16) __half g_xr_hi [T_SZ * BH];
__device__ __align__(16) __half g_xr_lo [T_SZ * BH];
__device__ __align__(16) __half g_hs0_hi[T_SZ * BH];
__device__ __align__(16) __half g_hs0_lo[T_SZ * BH];
__device__ __align__(16) __half g_h1_hi [2][BH];
__device__ __align__(16) __half g_h1_lo [2][BH];
__device__ __align__(16) __half g_zero_h[BH];          // never written -> zero
__device__ __align__(16) float  g_c[2][BH];
__device__ __align__(16) __half g_Wp[2][NG * KC];      // fp16 weights [n'][K], n'=4j+g
__device__ __align__(16) float  g_biasP[2][NG];

// ---------------------------------------------------------------------------
// PTX helpers (plain sm_100: cp.async + ldmatrix + mma.sync)
// ---------------------------------------------------------------------------
__device__ __forceinline__ uint32_t smem_u32(const void* p) {
    uint32_t a;
    asm("{ .reg .u64 t; cvta.to.shared.u64 t, %1; cvt.u32.u64 %0, t; }" : "=r"(a) : "l"(p));
    return a;
}
__device__ __forceinline__ void cpasync16(uint32_t s, const void* g) {
    asm volatile("cp.async.cg.shared.global [%0], [%1], 16;" :: "r"(s), "l"(g));
}
#define CP_COMMIT() asm volatile("cp.async.commit_group;" ::: "memory")
#define CP_WAIT1()  asm volatile("cp.async.wait_group 1;" ::: "memory")
#define CP_WAIT0()  asm volatile("cp.async.wait_group 0;" ::: "memory")

#define LDSM4(r0, r1, r2, r3, addr) asm volatile( \
    "ldmatrix.sync.aligned.m8n8.x4.shared.b16 {%0,%1,%2,%3}, [%4];" \
    : "=r"(r0), "=r"(r1), "=r"(r2), "=r"(r3) : "r"(addr))

#define MMA16816(d, a, b) asm volatile( \
    "mma.sync.aligned.m16n8k16.row.col.f32.f16.f16.f32 " \
    "{%0,%1,%2,%3}, {%4,%5,%6,%7}, {%8,%9}, {%0,%1,%2,%3};" \
    : "+f"((d)[0]), "+f"((d)[1]), "+f"((d)[2]), "+f"((d)[3]) \
    : "r"((a)[0]), "r"((a)[1]), "r"((a)[2]), "r"((a)[3]), "r"((b)[0]), "r"((b)[1]))

// SMEM layout: 2 pipeline stages + DEDICATED gates region (no aliasing).
// Per chunk (BK=64): tiles 128 rows x 64 fp16 (128B) padded to 144B pitch.
//   stage = {Ahi, Alo, B} = 55296B
#define PITCH    144
#define TILE_B   18432                 // 128*144
#define BUF_SZ   (3 * TILE_B)          // 55296
#define OFF_AHI(b) ((b) * BUF_SZ)
#define OFF_ALO(b) ((b) * BUF_SZ + TILE_B)
#define OFF_B(b)   ((b) * BUF_SZ + 2 * TILE_B)
#define OFF_GATES  (2 * BUF_SZ)        // 110592: float[128][132]
#define SMEM_TOTAL (OFF_GATES + 128 * 132 * 4)   // 178176

__device__ __forceinline__ float fsigm(float x) {
    x = fminf(fmaxf(x, -30.f), 30.f);
    return __fdividef(1.f, 1.f + __expf(-x));
}
__device__ __forceinline__ float ftanh(float x) {
    x = fminf(fmaxf(x, -15.f), 15.f);
    float e = __expf(2.f * x);
    return (e - 1.f) * __fdividef(1.f, e + 1.f);
}

// ---------------------------------------------------------------------------
// Prep kernels
// ---------------------------------------------------------------------------
__global__ void prep_weights(const float* __restrict__ wih0, const float* __restrict__ whh0,
                             const float* __restrict__ wih1, const float* __restrict__ whh1) {
    int id = blockIdx.x * blockDim.x + threadIdx.x;
    if (id >= 2 * NG * KC) return;
    int layer = id >> 19;
    int rem   = id & ((1 << 19) - 1);
    int np = rem >> 9;
    int k  = rem & 511;
    int j = np >> 2, g = np & 3;
    int n = g * H_SZ + j;
    const float* wih = layer ? wih1 : wih0;
    const float* whh = layer ? whh1 : whh0;
    float w = (k < H_SZ) ? wih[n * H_SZ + k] : whh[n * H_SZ + (k - H_SZ)];
    g_Wp[layer][np * KC + k] = __float2half(w);
}

__global__ void prep_misc(const float* __restrict__ bih0, const float* __restrict__ bhh0,
                          const float* __restrict__ bih1, const float* __restrict__ bhh1) {
    int id = blockIdx.x * blockDim.x + threadIdx.x;
    if (id < BH)          g_c[0][id] = 0.0f;
    else if (id < 2 * BH) g_c[1][id - BH] = 0.0f;
    else if (id < 2 * BH + 2 * NG) {
        int r = id - 2 * BH;
        int layer = r >> 10;
        int np = r & 1023;
        int j = np >> 2, g = np & 3;
        int n = g * H_SZ + j;
        const float* bi = layer ? bih1 : bih0;
        const float* bh = layer ? bhh1 : bhh0;
        g_biasP[layer][np] = bi[n] + bh[n];
    }
}

// relu + [B,T,H]->[T,B,H] + fp16 hi/lo split
__global__ void relu_split(const float* __restrict__ x) {
    int id = blockIdx.x * blockDim.x + threadIdx.x;
    if (id >= T_SZ * B_SZ * (H_SZ / 4)) return;
    int t   = id / (B_SZ * (H_SZ / 4));
    int rem = id % (B_SZ * (H_SZ / 4));
    int b   = rem / (H_SZ / 4);
    int e4  = rem % (H_SZ / 4);
    float4 v = *(const float4*)(x + (size_t)b * T_SZ * H_SZ + t * H_SZ + e4 * 4);
    v.x = fmaxf(v.x, 0.f); v.y = fmaxf(v.y, 0.f);
    v.z = fmaxf(v.z, 0.f); v.w = fmaxf(v.w, 0.f);
    size_t o = (size_t)t * BH + b * H_SZ + e4 * 4;
    __half hx = __float2half(v.x), hy = __float2half(v.y);
    __half hz = __float2half(v.z), hw = __float2half(v.w);
    g_xr_hi[o]     = hx;  g_xr_hi[o + 1] = hy;
    g_xr_hi[o + 2] = hz;  g_xr_hi[o + 3] = hw;
    g_xr_lo[o]     = __float2half(v.x - __half2float(hx));
    g_xr_lo[o + 1] = __float2half(v.y - __half2float(hy));
    g_xr_lo[o + 2] = __float2half(v.z - __half2float(hz));
    g_xr_lo[o + 3] = __float2half(v.w - __half2float(hw));
}

// ---------------------------------------------------------------------------
// LSTM wavefront u: layer 0 does t=u, layer 1 does t=u-1.
// grid (8, 8, 2) = 128 CTAs, 512 threads. CTA tile 128x128, K=512, BK=64.
// 2-stage cp.async pipeline (R7/R9-proven). Warp layout 4m x 4n (32x32).
// fp16 split: A = Ahi+Alo (~22-bit), B = single fp16. 2 products per k-step.
// ---------------------------------------------------------------------------
__global__ __launch_bounds__(512, 1) void lstm_step_mma(int u) {
    const int layer = blockIdx.z;
    const int t = u - layer;
    if (t < 0 || t >= T_SZ) return;

    extern __shared__ char smem[];
    const uint32_t sb = smem_u32(smem);
    const int tid  = threadIdx.x;
    const int lane = tid & 31;
    const int wid  = tid >> 5;
    const int wm   = wid & 3;        // 4 m-warps (32 rows each)
    const int wn   = wid >> 2;       // 4 n-warps (32 cols each)
    const int n0 = blockIdx.x * 128;
    const int m0 = blockIdx.y * 128;

    // operand sources
    const __half *xh, *xl, *hh, *hl;
    if (layer == 0) {
        xh = g_xr_hi + (size_t)t * BH;  xl = g_xr_lo + (size_t)t * BH;
        if (t == 0) { hh = g_zero_h; hl = g_zero_h; }
        else { hh = g_hs0_hi + (size_t)(t - 1) * BH; hl = g_hs0_lo + (size_t)(t - 1) * BH; }
    } else {
        xh = g_hs0_hi + (size_t)t * BH; xl = g_hs0_lo + (size_t)t * BH;
        if (t == 0) { hh = g_zero_h; hl = g_zero_h; }
        else { hh = g_h1_hi[(t - 1) & 1]; hl = g_h1_lo[(t - 1) & 1]; }
    }
    __half* out_hi = (layer == 0) ? (g_hs0_hi + (size_t)t * BH) : g_h1_hi[t & 1];
    __half* out_lo = (layer == 0) ? (g_hs0_lo + (size_t)t * BH) : g_h1_lo[t & 1];
    float* cst = g_c[layer];
    const __half* WP = g_Wp[layer];

    // ---- chunk loader: BK=64, 2 rotating buffers ----
    auto load_chunk = [&](int ck) {
        const int buf = ck & 1;
        const int kk = ck * 64;
        const __half* ah = (kk < H_SZ) ? xh : hh;
        const __half* al = (kk < H_SZ) ? xl : hl;
        const int koff = kk & (H_SZ - 1);
        #pragma unroll
        for (int i = 0; i < 2; i++) {
            int idx = tid + i * 512;              // 0..1023
            int row = idx >> 3, c16 = idx & 7;
            size_t ga = (size_t)(m0 + row) * H_SZ + koff + c16 * 8;
            uint32_t so = sb + OFF_AHI(buf) + row * PITCH + c16 * 16;
            cpasync16(so, ah + ga);
            cpasync16(so + TILE_B, al + ga);
            size_t gb = (size_t)(n0 + row) * KC + kk + c16 * 8;
            cpasync16(sb + OFF_B(buf) + row * PITCH + c16 * 16, WP + gb);
        }
        CP_COMMIT();
    };

    float acc[2][4][4];
    #pragma unroll
    for (int a = 0; a < 2; a++)
        #pragma unroll
        for (int b = 0; b < 4; b++)
            #pragma unroll
            for (int q = 0; q < 4; q++) acc[a][b][q] = 0.f;

    load_chunk(0);

    const uint32_t a_lane = (uint32_t)((lane & 15) * PITCH + ((lane >> 4) << 4));
    const uint32_t b_lane = (uint32_t)(((lane & 7) + ((lane >> 4) & 1) * 8) * PITCH +
                                       ((lane >> 3) & 1) * 16);

    #pragma unroll 1
    for (int ck = 0; ck < 8; ck++) {
        const int buf = ck & 1;
        if (ck < 7) load_chunk(ck + 1);
        if (ck < 7) { CP_WAIT1(); } else { CP_WAIT0(); }
        __syncthreads();

        #pragma unroll
        for (int ks = 0; ks < 4; ks++) {
            const uint32_t kso = (uint32_t)(ks * 32);
            // --- fragment loads: B, A-hi ---
            uint32_t bf[4][2];
            #pragma unroll
            for (int blk = 0; blk < 2; blk++) {
                uint32_t ad = sb + OFF_B(buf) + (wn * 32 + blk * 16) * PITCH + kso + b_lane;
                LDSM4(bf[blk * 2][0], bf[blk * 2][1], bf[blk * 2 + 1][0], bf[blk * 2 + 1][1], ad);
            }
            uint32_t ah_f[2][4];
            #pragma unroll
            for (int mf = 0; mf < 2; mf++) {
                uint32_t ad = sb + OFF_AHI(buf) + (wm * 32 + mf * 16) * PITCH + kso + a_lane;
                LDSM4(ah_f[mf][0], ah_f[mf][1], ah_f[mf][2], ah_f[mf][3], ad);
            }
            // --- pass 1: Ahi x B (8 MMAs, distinct accumulators) ---
            #pragma unroll
            for (int mf = 0; mf < 2; mf++)
                #pragma unroll
                for (int nf = 0; nf < 4; nf++)
                    MMA16816(acc[mf][nf], ah_f[mf], bf[nf]);
            // --- A-lo LDSM here: latency hidden under pass 1's MMAs ---
            uint32_t al_f[2][4];
            #pragma unroll
            for (int mf = 0; mf < 2; mf++) {
                uint32_t ad = sb + OFF_ALO(buf) + (wm * 32 + mf * 16) * PITCH + kso + a_lane;
                LDSM4(al_f[mf][0], al_f[mf][1], al_f[mf][2], al_f[mf][3], ad);
            }
            // --- pass 2: Alo x B ---
            #pragma unroll
            for (int mf = 0; mf < 2; mf++)
                #pragma unroll
                for (int nf = 0; nf < 4; nf++)
                    MMA16816(acc[mf][nf], al_f[mf], bf[nf]);
        }
        __syncthreads();
    }

    // ---- stage gates to DEDICATED SMEM region: float[128][132] ----
    float* gates = (float*)(smem + OFF_GATES);
    #pragma unroll
    for (int mf = 0; mf < 2; mf++)
        #pragma unroll
        for (int nf = 0; nf < 4; nf++) {
            int r = wm * 32 + mf * 16 + (lane >> 2);
            int cc = wn * 32 + nf * 8 + (lane & 3) * 2;
            gates[r * 132 + cc]           = acc[mf][nf][0];
            gates[r * 132 + cc + 1]       = acc[mf][nf][1];
            gates[(r + 8) * 132 + cc]     = acc[mf][nf][2];
            gates[(r + 8) * 132 + cc + 1] = acc[mf][nf][3];
        }
    __syncthreads();

    // ---- fused LSTM pointwise: 128 rows x 32 hidden units per CTA ----
    const int j0 = n0 >> 2;
    const float* bp = g_biasP[layer] + n0;
    #pragma unroll
    for (int i = 0; i < 8; i++) {
        int e = i * 512 + tid;
        int row = e >> 5, j = e & 31;
        float4 bq = *(const float4*)(bp + 4 * j);
        float4 gq = *(const float4*)(gates + row * 132 + 4 * j);
        float gi = gq.x + bq.x, gf = gq.y + bq.y, gg = gq.z + bq.z, go = gq.w + bq.w;
        size_t ci = (size_t)(m0 + row) * H_SZ + j0 + j;
        float cold = cst[ci];
        float cn = fsigm(gf) * cold + fsigm(gi) * ftanh(gg);
        float hn = fsigm(go) * ftanh(cn);
        cst[ci] = cn;
        __half hb = __float2half(hn);
        out_hi[ci] = hb;
        out_lo[ci] = __float2half(hn - __half2float(hb));
    }
}

// ---------------------------------------------------------------------------
// FC head (reads h = hi + lo)
// ---------------------------------------------------------------------------
__global__ __launch_bounds__(128) void fc_head(const float* __restrict__ fc1w,
                                               const float* __restrict__ fc1b,
                                               const float* __restrict__ fc2w,
                                               const float* __restrict__ fc2b,
                                               float* __restrict__ out) {
    __shared__ float sh[H_SZ];
    __shared__ float red[128];
    const int b = blockIdx.x, t = threadIdx.x;
    const __half* hh = g_h1_hi[(T_SZ - 1) & 1];
    const __half* hl = g_h1_lo[(T_SZ - 1) & 1];
    sh[t]       = __half2float(hh[b * H_SZ + t])       + __half2float(hl[b * H_SZ + t]);
    sh[t + 128] = __half2float(hh[b * H_SZ + t + 128]) + __half2float(hl[b * H_SZ + t + 128]);
    __syncthreads();
    float acc = 0.f;
    const float* wr = fc1w + t * H_SZ;
    #pragma unroll 8
    for (int k = 0; k < H_SZ; k++) acc += sh[k] * wr[k];
    acc += fc1b[t];
    acc = fmaxf(acc, 0.f) * fc2w[t];
    red[t] = acc;
    __syncthreads();
    for (int s = 64; s > 0; s >>= 1) {
        if (t < s) red[t] += red[t + s];
        __syncthreads();
    }
    if (t == 0) out[b] = 1.f / (1.f + expf(-(red[0] + fc2b[0])));
}

// ---------------------------------------------------------------------------
// Launch
// ---------------------------------------------------------------------------
extern "C" void kernel_launch(void* const* d_in, const int* in_sizes, int n_in,
                              void* d_out, int out_size) {
    const float* x    = (const float*)d_in[0];
    const float* wih0 = (const float*)d_in[1];
    const float* whh0 = (const float*)d_in[2];
    const float* bih0 = (const float*)d_in[3];
    const float* bhh0 = (const float*)d_in[4];
    const float* wih1 = (const float*)d_in[5];
    const float* whh1 = (const float*)d_in[6];
    const float* bih1 = (const float*)d_in[7];
    const float* bhh1 = (const float*)d_in[8];
    const float* fc1w = (const float*)d_in[9];
    const float* fc1b = (const float*)d_in[10];
    const float* fc2w = (const float*)d_in[11];
    const float* fc2b = (const float*)d_in[12];
    float* out = (float*)d_out;

    cudaFuncSetAttribute(lstm_step_mma, cudaFuncAttributeMaxDynamicSharedMemorySize, SMEM_TOTAL);

    prep_weights<<<(2 * NG * KC + 255) / 256, 256>>>(wih0, whh0, wih1, whh1);
    prep_misc<<<(2 * BH + 2 * NG + 255) / 256, 256>>>(bih0, bhh0, bih1, bhh1);
    relu_split<<<(T_SZ * B_SZ * (H_SZ / 4) + 255) / 256, 256>>>(x);

    dim3 grid(NG / 128, B_SZ / 128, 2);   // (8, 8, 2) = 128 CTAs x 512 threads
    for (int u = 0; u <= T_SZ; u++) lstm_step_mma<<<grid, 512, SMEM_TOTAL>>>(u);

    fc_head<<<B_SZ, 128>>>(fc1w, fc1b, fc2w, fc2b, out);
}

// round 13
// speedup vs baseline: 8.0346x; 1.3833x over previous
#include <cuda_runtime.h>
#include <cuda_fp16.h>
#include <cstdint>
#include <math.h>

#define B_SZ 1024
#define T_SZ 128
#define H_SZ 256
#define NG   1024            // 4*H
#define KC   512             // combined K (x | h)
#define BH   (B_SZ * H_SZ)

// ---------------------------------------------------------------------------
// Static device scratch (no cudaMalloc anywhere)
// ---------------------------------------------------------------------------
__device__ __align__(16) __half g_xr  [T_SZ * BH];     // relu(x) time-major fp16
__device__ __align__(16) __half g_hs0 [T_SZ * BH];     // layer-0 h outputs fp16
__device__ __align__(16) __half g_h1  [2][BH];         // layer-1 h double buffered
__device__ __align__(16) __half g_zero_h[BH];          // never written -> zero
__device__ __align__(16) float  g_c[2][BH];
__device__ __align__(16) __half g_Wp[2][NG * KC];      // fp16 weights [n'][K], n'=4j+g
__device__ __align__(16) float  g_biasP[2][NG];

// ---------------------------------------------------------------------------
// PTX helpers (plain sm_100: cp.async + ldmatrix + mma.sync)
// ---------------------------------------------------------------------------
__device__ __forceinline__ uint32_t smem_u32(const void* p) {
    uint32_t a;
    asm("{ .reg .u64 t; cvta.to.shared.u64 t, %1; cvt.u32.u64 %0, t; }" : "=r"(a) : "l"(p));
    return a;
}
__device__ __forceinline__ void cpasync16(uint32_t s, const void* g) {
    asm volatile("cp.async.cg.shared.global [%0], [%1], 16;" :: "r"(s), "l"(g));
}
#define CP_COMMIT() asm volatile("cp.async.commit_group;" ::: "memory")
#define CP_WAIT1()  asm volatile("cp.async.wait_group 1;" ::: "memory")
#define CP_WAIT0()  asm volatile("cp.async.wait_group 0;" ::: "memory")

#define LDSM4(r0, r1, r2, r3, addr) asm volatile( \
    "ldmatrix.sync.aligned.m8n8.x4.shared.b16 {%0,%1,%2,%3}, [%4];" \
    : "=r"(r0), "=r"(r1), "=r"(r2), "=r"(r3) : "r"(addr))

#define MMA16816(d, a, b) asm volatile( \
    "mma.sync.aligned.m16n8k16.row.col.f32.f16.f16.f32 " \
    "{%0,%1,%2,%3}, {%4,%5,%6,%7}, {%8,%9}, {%0,%1,%2,%3};" \
    : "+f"((d)[0]), "+f"((d)[1]), "+f"((d)[2]), "+f"((d)[3]) \
    : "r"((a)[0]), "r"((a)[1]), "r"((a)[2]), "r"((a)[3]), "r"((b)[0]), "r"((b)[1]))

// SMEM layout: 2 pipeline stages + DEDICATED gates region (R12-proven scheme).
// Per chunk (BK=64): tiles 128 rows x 64 fp16 (128B) padded to 144B pitch.
//   stage = {A, B} = 36864B
#define PITCH    144
#define TILE_B   18432                 // 128*144
#define BUF_SZ   (2 * TILE_B)          // 36864
#define OFF_A(b)   ((b) * BUF_SZ)
#define OFF_B(b)   ((b) * BUF_SZ + TILE_B)
#define OFF_GATES  (2 * BUF_SZ)        // 73728: float[128][132]
#define SMEM_TOTAL (OFF_GATES + 128 * 132 * 4)   // 141312

__device__ __forceinline__ float fsigm(float x) {
    x = fminf(fmaxf(x, -30.f), 30.f);
    return __fdividef(1.f, 1.f + __expf(-x));
}
__device__ __forceinline__ float ftanh(float x) {
    x = fminf(fmaxf(x, -15.f), 15.f);
    float e = __expf(2.f * x);
    return (e - 1.f) * __fdividef(1.f, e + 1.f);
}

// ---------------------------------------------------------------------------
// Prep kernels
// ---------------------------------------------------------------------------
__global__ void prep_weights(const float* __restrict__ wih0, const float* __restrict__ whh0,
                             const float* __restrict__ wih1, const float* __restrict__ whh1) {
    int id = blockIdx.x * blockDim.x + threadIdx.x;
    if (id >= 2 * NG * KC) return;
    int layer = id >> 19;
    int rem   = id & ((1 << 19) - 1);
    int np = rem >> 9;
    int k  = rem & 511;
    int j = np >> 2, g = np & 3;
    int n = g * H_SZ + j;
    const float* wih = layer ? wih1 : wih0;
    const float* whh = layer ? whh1 : whh0;
    float w = (k < H_SZ) ? wih[n * H_SZ + k] : whh[n * H_SZ + (k - H_SZ)];
    g_Wp[layer][np * KC + k] = __float2half(w);
}

__global__ void prep_misc(const float* __restrict__ bih0, const float* __restrict__ bhh0,
                          const float* __restrict__ bih1, const float* __restrict__ bhh1) {
    int id = blockIdx.x * blockDim.x + threadIdx.x;
    if (id < BH)          g_c[0][id] = 0.0f;
    else if (id < 2 * BH) g_c[1][id - BH] = 0.0f;
    else if (id < 2 * BH + 2 * NG) {
        int r = id - 2 * BH;
        int layer = r >> 10;
        int np = r & 1023;
        int j = np >> 2, g = np & 3;
        int n = g * H_SZ + j;
        const float* bi = layer ? bih1 : bih0;
        const float* bh = layer ? bhh1 : bhh0;
        g_biasP[layer][np] = bi[n] + bh[n];
    }
}

// relu + [B,T,H]->[T,B,H] + fp16 convert
__global__ void relu_cvt(const float* __restrict__ x) {
    int id = blockIdx.x * blockDim.x + threadIdx.x;
    if (id >= T_SZ * B_SZ * (H_SZ / 4)) return;
    int t   = id / (B_SZ * (H_SZ / 4));
    int rem = id % (B_SZ * (H_SZ / 4));
    int b   = rem / (H_SZ / 4);
    int e4  = rem % (H_SZ / 4);
    float4 v = *(const float4*)(x + (size_t)b * T_SZ * H_SZ + t * H_SZ + e4 * 4);
    size_t o = (size_t)t * BH + b * H_SZ + e4 * 4;
    g_xr[o]     = __float2half(fmaxf(v.x, 0.f));
    g_xr[o + 1] = __float2half(fmaxf(v.y, 0.f));
    g_xr[o + 2] = __float2half(fmaxf(v.z, 0.f));
    g_xr[o + 3] = __float2half(fmaxf(v.w, 0.f));
}

// ---------------------------------------------------------------------------
// LSTM wavefront u: layer 0 does t=u, layer 1 does t=u-1.
// grid (8, 8, 2) = 128 CTAs, 512 threads. CTA tile 128x128, K=512, BK=64.
// 2-stage cp.async pipeline (R12-proven). Warp layout 4m x 4n (32x32).
// Pure fp16 single product: 8 MMAs + 4 LDSM per k-step.
// ---------------------------------------------------------------------------
__global__ __launch_bounds__(512, 1) void lstm_step_mma(int u) {
    const int layer = blockIdx.z;
    const int t = u - layer;
    if (t < 0 || t >= T_SZ) return;

    extern __shared__ char smem[];
    const uint32_t sb = smem_u32(smem);
    const int tid  = threadIdx.x;
    const int lane = tid & 31;
    const int wid  = tid >> 5;
    const int wm   = wid & 3;        // 4 m-warps (32 rows each)
    const int wn   = wid >> 2;       // 4 n-warps (32 cols each)
    const int n0 = blockIdx.x * 128;
    const int m0 = blockIdx.y * 128;

    // operand sources
    const __half *xs, *hs;
    if (layer == 0) {
        xs = g_xr + (size_t)t * BH;
        hs = (t == 0) ? g_zero_h : (g_hs0 + (size_t)(t - 1) * BH);
    } else {
        xs = g_hs0 + (size_t)t * BH;
        hs = (t == 0) ? g_zero_h : g_h1[(t - 1) & 1];
    }
    __half* outp = (layer == 0) ? (g_hs0 + (size_t)t * BH) : g_h1[t & 1];
    float* cst = g_c[layer];
    const __half* WP = g_Wp[layer];

    // ---- chunk loader: BK=64, 2 rotating buffers ----
    auto load_chunk = [&](int ck) {
        const int buf = ck & 1;
        const int kk = ck * 64;
        const __half* asrc = (kk < H_SZ) ? xs : hs;
        const int koff = kk & (H_SZ - 1);
        #pragma unroll
        for (int i = 0; i < 2; i++) {
            int idx = tid + i * 512;              // 0..1023
            int row = idx >> 3, c16 = idx & 7;
            size_t ga = (size_t)(m0 + row) * H_SZ + koff + c16 * 8;
            cpasync16(sb + OFF_A(buf) + row * PITCH + c16 * 16, asrc + ga);
            size_t gb = (size_t)(n0 + row) * KC + kk + c16 * 8;
            cpasync16(sb + OFF_B(buf) + row * PITCH + c16 * 16, WP + gb);
        }
        CP_COMMIT();
    };

    float acc[2][4][4];
    #pragma unroll
    for (int a = 0; a < 2; a++)
        #pragma unroll
        for (int b = 0; b < 4; b++)
            #pragma unroll
            for (int q = 0; q < 4; q++) acc[a][b][q] = 0.f;

    load_chunk(0);

    const uint32_t a_lane = (uint32_t)((lane & 15) * PITCH + ((lane >> 4) << 4));
    const uint32_t b_lane = (uint32_t)(((lane & 7) + ((lane >> 4) & 1) * 8) * PITCH +
                                       ((lane >> 3) & 1) * 16);

    #pragma unroll 1
    for (int ck = 0; ck < 8; ck++) {
        const int buf = ck & 1;
        if (ck < 7) load_chunk(ck + 1);
        if (ck < 7) { CP_WAIT1(); } else { CP_WAIT0(); }
        __syncthreads();

        #pragma unroll
        for (int ks = 0; ks < 4; ks++) {
            const uint32_t kso = (uint32_t)(ks * 32);
            uint32_t bf[4][2];
            #pragma unroll
            for (int blk = 0; blk < 2; blk++) {
                uint32_t ad = sb + OFF_B(buf) + (wn * 32 + blk * 16) * PITCH + kso + b_lane;
                LDSM4(bf[blk * 2][0], bf[blk * 2][1], bf[blk * 2 + 1][0], bf[blk * 2 + 1][1], ad);
            }
            uint32_t af[2][4];
            #pragma unroll
            for (int mf = 0; mf < 2; mf++) {
                uint32_t ad = sb + OFF_A(buf) + (wm * 32 + mf * 16) * PITCH + kso + a_lane;
                LDSM4(af[mf][0], af[mf][1], af[mf][2], af[mf][3], ad);
            }
            #pragma unroll
            for (int mf = 0; mf < 2; mf++)
                #pragma unroll
                for (int nf = 0; nf < 4; nf++)
                    MMA16816(acc[mf][nf], af[mf], bf[nf]);
        }
        __syncthreads();
    }

    // ---- stage gates to DEDICATED SMEM region: float[128][132] ----
    float* gates = (float*)(smem + OFF_GATES);
    #pragma unroll
    for (int mf = 0; mf < 2; mf++)
        #pragma unroll
        for (int nf = 0; nf < 4; nf++) {
            int r = wm * 32 + mf * 16 + (lane >> 2);
            int cc = wn * 32 + nf * 8 + (lane & 3) * 2;
            gates[r * 132 + cc]           = acc[mf][nf][0];
            gates[r * 132 + cc + 1]       = acc[mf][nf][1];
            gates[(r + 8) * 132 + cc]     = acc[mf][nf][2];
            gates[(r + 8) * 132 + cc + 1] = acc[mf][nf][3];
        }
    __syncthreads();

    // ---- fused LSTM pointwise: 128 rows x 32 hidden units per CTA ----
    const int j0 = n0 >> 2;
    const float* bp = g_biasP[layer] + n0;
    #pragma unroll
    for (int i = 0; i < 8; i++) {
        int e = i * 512 + tid;
        int row = e >> 5, j = e & 31;
        float4 bq = *(const float4*)(bp + 4 * j);
        float4 gq = *(const float4*)(gates + row * 132 + 4 * j);
        float gi = gq.x + bq.x, gf = gq.y + bq.y, gg = gq.z + bq.z, go = gq.w + bq.w;
        size_t ci = (size_t)(m0 + row) * H_SZ + j0 + j;
        float cold = cst[ci];
        float cn = fsigm(gf) * cold + fsigm(gi) * ftanh(gg);
        float hn = fsigm(go) * ftanh(cn);
        cst[ci] = cn;
        outp[ci] = __float2half(hn);
    }
}

// ---------------------------------------------------------------------------
// FC head
// ---------------------------------------------------------------------------
__global__ __launch_bounds__(128) void fc_head(const float* __restrict__ fc1w,
                                               const float* __restrict__ fc1b,
                                               const float* __restrict__ fc2w,
                                               const float* __restrict__ fc2b,
                                               float* __restrict__ out) {
    __shared__ float sh[H_SZ];
    __shared__ float red[128];
    const int b = blockIdx.x, t = threadIdx.x;
    const __half* hh = g_h1[(T_SZ - 1) & 1];
    sh[t]       = __half2float(hh[b * H_SZ + t]);
    sh[t + 128] = __half2float(hh[b * H_SZ + t + 128]);
    __syncthreads();
    float acc = 0.f;
    const float* wr = fc1w + t * H_SZ;
    #pragma unroll 8
    for (int k = 0; k < H_SZ; k++) acc += sh[k] * wr[k];
    acc += fc1b[t];
    acc = fmaxf(acc, 0.f) * fc2w[t];
    red[t] = acc;
    __syncthreads();
    for (int s = 64; s > 0; s >>= 1) {
        if (t < s) red[t] += red[t + s];
        __syncthreads();
    }
    if (t == 0) out[b] = 1.f / (1.f + expf(-(red[0] + fc2b[0])));
}

// ---------------------------------------------------------------------------
// Launch
// ---------------------------------------------------------------------------
extern "C" void kernel_launch(void* const* d_in, const int* in_sizes, int n_in,
                              void* d_out, int out_size) {
    const float* x    = (const float*)d_in[0];
    const float* wih0 = (const float*)d_in[1];
    const float* whh0 = (const float*)d_in[2];
    const float* bih0 = (const float*)d_in[3];
    const float* bhh0 = (const float*)d_in[4];
    const float* wih1 = (const float*)d_in[5];
    const float* whh1 = (const float*)d_in[6];
    const float* bih1 = (const float*)d_in[7];
    const float* bhh1 = (const float*)d_in[8];
    const float* fc1w = (const float*)d_in[9];
    const float* fc1b = (const float*)d_in[10];
    const float* fc2w = (const float*)d_in[11];
    const float* fc2b = (const float*)d_in[12];
    float* out = (float*)d_out;

    cudaFuncSetAttribute(lstm_step_mma, cudaFuncAttributeMaxDynamicSharedMemorySize, SMEM_TOTAL);

    prep_weights<<<(2 * NG * KC + 255) / 256, 256>>>(wih0, whh0, wih1, whh1);
    prep_misc<<<(2 * BH + 2 * NG + 255) / 256, 256>>>(bih0, bhh0, bih1, bhh1);
    relu_cvt<<<(T_SZ * B_SZ * (H_SZ / 4) + 255) / 256, 256>>>(x);

    dim3 grid(NG / 128, B_SZ / 128, 2);   // (8, 8, 2) = 128 CTAs x 512 threads
    for (int u = 0; u <= T_SZ; u++) lstm_step_mma<<<grid, 512, SMEM_TOTAL>>>(u);

    fc_head<<<B_SZ, 128>>>(fc1w, fc1b, fc2w, fc2b, out);
}

// round 14
// speedup vs baseline: 8.5038x; 1.0584x over previous
#include <cuda_runtime.h>
#include <cuda_fp16.h>
#include <cstdint>
#include <math.h>

#define B_SZ 1024
#define T_SZ 128
#define H_SZ 256
#define NG   1024            // 4*H
#define KC   512             // combined K (x | h)
#define BH   (B_SZ * H_SZ)

// ---------------------------------------------------------------------------
// Static device scratch (no cudaMalloc anywhere)
// ---------------------------------------------------------------------------
__device__ __align__(16) __half g_xr  [T_SZ * BH];     // relu(x) time-major fp16
__device__ __align__(16) __half g_hs0 [T_SZ * BH];     // layer-0 h outputs fp16
__device__ __align__(16) __half g_h1  [2][BH];         // layer-1 h double buffered
__device__ __align__(16) __half g_zero_h[BH];          // never written -> zero
__device__ __align__(16) float  g_c[2][BH];
__device__ __align__(16) __half g_Wp[2][NG * KC];      // fp16 weights [n'][K], n'=4j+g
__device__ __align__(16) float  g_biasP[2][NG];

// ---------------------------------------------------------------------------
// PTX helpers (plain sm_100: cp.async + ldmatrix + mma.sync)
// ---------------------------------------------------------------------------
__device__ __forceinline__ uint32_t smem_u32(const void* p) {
    uint32_t a;
    asm("{ .reg .u64 t; cvta.to.shared.u64 t, %1; cvt.u32.u64 %0, t; }" : "=r"(a) : "l"(p));
    return a;
}
__device__ __forceinline__ void cpasync16(uint32_t s, const void* g) {
    asm volatile("cp.async.cg.shared.global [%0], [%1], 16;" :: "r"(s), "l"(g));
}
#define CP_COMMIT() asm volatile("cp.async.commit_group;" ::: "memory")
#define CP_WAIT1()  asm volatile("cp.async.wait_group 1;" ::: "memory")
#define CP_WAIT0()  asm volatile("cp.async.wait_group 0;" ::: "memory")

#define LDSM4(r0, r1, r2, r3, addr) asm volatile( \
    "ldmatrix.sync.aligned.m8n8.x4.shared.b16 {%0,%1,%2,%3}, [%4];" \
    : "=r"(r0), "=r"(r1), "=r"(r2), "=r"(r3) : "r"(addr))

#define MMA16816(d, a, b) asm volatile( \
    "mma.sync.aligned.m16n8k16.row.col.f32.f16.f16.f32 " \
    "{%0,%1,%2,%3}, {%4,%5,%6,%7}, {%8,%9}, {%0,%1,%2,%3};" \
    : "+f"((d)[0]), "+f"((d)[1]), "+f"((d)[2]), "+f"((d)[3]) \
    : "r"((a)[0]), "r"((a)[1]), "r"((a)[2]), "r"((a)[3]), "r"((b)[0]), "r"((b)[1]))

// SMEM layout: 2 pipeline stages (BK=128) + DEDICATED gates region.
// Per chunk: tiles 128 rows x 128 fp16 (256B) padded to 272B pitch.
//   bank pattern: row-start bank = (272/4 * r) mod 32 = 4r mod 32 — identical
//   to the proven 144B pitch; ldmatrix stays conflict-free.
//   stage = {A, B} = 69632B
#define PITCH    272
#define TILE_B   34816                 // 128*272
#define BUF_SZ   (2 * TILE_B)          // 69632
#define OFF_A(b)   ((b) * BUF_SZ)
#define OFF_B(b)   ((b) * BUF_SZ + TILE_B)
#define OFF_GATES  (2 * BUF_SZ)        // 139264: float[128][132]
#define SMEM_TOTAL (OFF_GATES + 128 * 132 * 4)   // 206848

__device__ __forceinline__ float fsigm(float x) {
    x = fminf(fmaxf(x, -30.f), 30.f);
    return __fdividef(1.f, 1.f + __expf(-x));
}
__device__ __forceinline__ float ftanh(float x) {
    x = fminf(fmaxf(x, -15.f), 15.f);
    float e = __expf(2.f * x);
    return (e - 1.f) * __fdividef(1.f, e + 1.f);
}

// ---------------------------------------------------------------------------
// Prep kernels
// ---------------------------------------------------------------------------
__global__ void prep_weights(const float* __restrict__ wih0, const float* __restrict__ whh0,
                             const float* __restrict__ wih1, const float* __restrict__ whh1) {
    int id = blockIdx.x * blockDim.x + threadIdx.x;
    if (id >= 2 * NG * KC) return;
    int layer = id >> 19;
    int rem   = id & ((1 << 19) - 1);
    int np = rem >> 9;
    int k  = rem & 511;
    int j = np >> 2, g = np & 3;
    int n = g * H_SZ + j;
    const float* wih = layer ? wih1 : wih0;
    const float* whh = layer ? whh1 : whh0;
    float w = (k < H_SZ) ? wih[n * H_SZ + k] : whh[n * H_SZ + (k - H_SZ)];
    g_Wp[layer][np * KC + k] = __float2half(w);
}

__global__ void prep_misc(const float* __restrict__ bih0, const float* __restrict__ bhh0,
                          const float* __restrict__ bih1, const float* __restrict__ bhh1) {
    int id = blockIdx.x * blockDim.x + threadIdx.x;
    if (id < BH)          g_c[0][id] = 0.0f;
    else if (id < 2 * BH) g_c[1][id - BH] = 0.0f;
    else if (id < 2 * BH + 2 * NG) {
        int r = id - 2 * BH;
        int layer = r >> 10;
        int np = r & 1023;
        int j = np >> 2, g = np & 3;
        int n = g * H_SZ + j;
        const float* bi = layer ? bih1 : bih0;
        const float* bh = layer ? bhh1 : bhh0;
        g_biasP[layer][np] = bi[n] + bh[n];
    }
}

// relu + [B,T,H]->[T,B,H] + fp16 convert
__global__ void relu_cvt(const float* __restrict__ x) {
    int id = blockIdx.x * blockDim.x + threadIdx.x;
    if (id >= T_SZ * B_SZ * (H_SZ / 4)) return;
    int t   = id / (B_SZ * (H_SZ / 4));
    int rem = id % (B_SZ * (H_SZ / 4));
    int b   = rem / (H_SZ / 4);
    int e4  = rem % (H_SZ / 4);
    float4 v = *(const float4*)(x + (size_t)b * T_SZ * H_SZ + t * H_SZ + e4 * 4);
    size_t o = (size_t)t * BH + b * H_SZ + e4 * 4;
    g_xr[o]     = __float2half(fmaxf(v.x, 0.f));
    g_xr[o + 1] = __float2half(fmaxf(v.y, 0.f));
    g_xr[o + 2] = __float2half(fmaxf(v.z, 0.f));
    g_xr[o + 3] = __float2half(fmaxf(v.w, 0.f));
}

// ---------------------------------------------------------------------------
// LSTM wavefront u: layer 0 does t=u, layer 1 does t=u-1.
// grid (8, 8, 2) = 128 CTAs, 512 threads. CTA tile 128x128, K=512, BK=128.
// 2-stage cp.async pipeline, 4 chunks -> 8 barriers total (was 16).
// Warp layout 4m x 4n (32x32). Pure fp16 single product.
// ---------------------------------------------------------------------------
__global__ __launch_bounds__(512, 1) void lstm_step_mma(int u) {
    const int layer = blockIdx.z;
    const int t = u - layer;
    if (t < 0 || t >= T_SZ) return;

    extern __shared__ char smem[];
    const uint32_t sb = smem_u32(smem);
    const int tid  = threadIdx.x;
    const int lane = tid & 31;
    const int wid  = tid >> 5;
    const int wm   = wid & 3;        // 4 m-warps (32 rows each)
    const int wn   = wid >> 2;       // 4 n-warps (32 cols each)
    const int n0 = blockIdx.x * 128;
    const int m0 = blockIdx.y * 128;

    // operand sources
    const __half *xs, *hs;
    if (layer == 0) {
        xs = g_xr + (size_t)t * BH;
        hs = (t == 0) ? g_zero_h : (g_hs0 + (size_t)(t - 1) * BH);
    } else {
        xs = g_hs0 + (size_t)t * BH;
        hs = (t == 0) ? g_zero_h : g_h1[(t - 1) & 1];
    }
    __half* outp = (layer == 0) ? (g_hs0 + (size_t)t * BH) : g_h1[t & 1];
    float* cst = g_c[layer];
    const __half* WP = g_Wp[layer];

    // ---- chunk loader: BK=128, 2 rotating buffers ----
    // A tile: 128 rows x 128 fp16 = 2048 16B-chunks -> 4 per thread
    // B tile: same.
    auto load_chunk = [&](int ck) {
        const int buf = ck & 1;
        const int kk = ck * 128;
        const __half* asrc = (kk < H_SZ) ? xs : hs;
        const int koff = kk & (H_SZ - 1);
        #pragma unroll
        for (int i = 0; i < 4; i++) {
            int idx = tid + i * 512;              // 0..2047
            int row = idx >> 4, c16 = idx & 15;
            size_t ga = (size_t)(m0 + row) * H_SZ + koff + c16 * 8;
            cpasync16(sb + OFF_A(buf) + row * PITCH + c16 * 16, asrc + ga);
            size_t gb = (size_t)(n0 + row) * KC + kk + c16 * 8;
            cpasync16(sb + OFF_B(buf) + row * PITCH + c16 * 16, WP + gb);
        }
        CP_COMMIT();
    };

    float acc[2][4][4];
    #pragma unroll
    for (int a = 0; a < 2; a++)
        #pragma unroll
        for (int b = 0; b < 4; b++)
            #pragma unroll
            for (int q = 0; q < 4; q++) acc[a][b][q] = 0.f;

    load_chunk(0);

    const uint32_t a_lane = (uint32_t)((lane & 15) * PITCH + ((lane >> 4) << 4));
    const uint32_t b_lane = (uint32_t)(((lane & 7) + ((lane >> 4) & 1) * 8) * PITCH +
                                       ((lane >> 3) & 1) * 16);

    #pragma unroll 1
    for (int ck = 0; ck < 4; ck++) {
        const int buf = ck & 1;
        if (ck < 3) load_chunk(ck + 1);
        if (ck < 3) { CP_WAIT1(); } else { CP_WAIT0(); }
        __syncthreads();

        #pragma unroll
        for (int ks = 0; ks < 8; ks++) {
            const uint32_t kso = (uint32_t)(ks * 32);
            uint32_t bf[4][2];
            #pragma unroll
            for (int blk = 0; blk < 2; blk++) {
                uint32_t ad = sb + OFF_B(buf) + (wn * 32 + blk * 16) * PITCH + kso + b_lane;
                LDSM4(bf[blk * 2][0], bf[blk * 2][1], bf[blk * 2 + 1][0], bf[blk * 2 + 1][1], ad);
            }
            uint32_t af[2][4];
            #pragma unroll
            for (int mf = 0; mf < 2; mf++) {
                uint32_t ad = sb + OFF_A(buf) + (wm * 32 + mf * 16) * PITCH + kso + a_lane;
                LDSM4(af[mf][0], af[mf][1], af[mf][2], af[mf][3], ad);
            }
            #pragma unroll
            for (int mf = 0; mf < 2; mf++)
                #pragma unroll
                for (int nf = 0; nf < 4; nf++)
                    MMA16816(acc[mf][nf], af[mf], bf[nf]);
        }
        __syncthreads();
    }

    // ---- stage gates to DEDICATED SMEM region: float[128][132] ----
    float* gates = (float*)(smem + OFF_GATES);
    #pragma unroll
    for (int mf = 0; mf < 2; mf++)
        #pragma unroll
        for (int nf = 0; nf < 4; nf++) {
            int r = wm * 32 + mf * 16 + (lane >> 2);
            int cc = wn * 32 + nf * 8 + (lane & 3) * 2;
            gates[r * 132 + cc]           = acc[mf][nf][0];
            gates[r * 132 + cc + 1]       = acc[mf][nf][1];
            gates[(r + 8) * 132 + cc]     = acc[mf][nf][2];
            gates[(r + 8) * 132 + cc + 1] = acc[mf][nf][3];
        }
    __syncthreads();

    // ---- fused LSTM pointwise: 128 rows x 32 hidden units per CTA ----
    const int j0 = n0 >> 2;
    const float* bp = g_biasP[layer] + n0;
    #pragma unroll
    for (int i = 0; i < 8; i++) {
        int e = i * 512 + tid;
        int row = e >> 5, j = e & 31;
        float4 bq = *(const float4*)(bp + 4 * j);
        float4 gq = *(const float4*)(gates + row * 132 + 4 * j);
        float gi = gq.x + bq.x, gf = gq.y + bq.y, gg = gq.z + bq.z, go = gq.w + bq.w;
        size_t ci = (size_t)(m0 + row) * H_SZ + j0 + j;
        float cold = cst[ci];
        float cn = fsigm(gf) * cold + fsigm(gi) * ftanh(gg);
        float hn = fsigm(go) * ftanh(cn);
        cst[ci] = cn;
        outp[ci] = __float2half(hn);
    }
}

// ---------------------------------------------------------------------------
// FC head
// ---------------------------------------------------------------------------
__global__ __launch_bounds__(128) void fc_head(const float* __restrict__ fc1w,
                                               const float* __restrict__ fc1b,
                                               const float* __restrict__ fc2w,
                                               const float* __restrict__ fc2b,
                                               float* __restrict__ out) {
    __shared__ float sh[H_SZ];
    __shared__ float red[128];
    const int b = blockIdx.x, t = threadIdx.x;
    const __half* hh = g_h1[(T_SZ - 1) & 1];
    sh[t]       = __half2float(hh[b * H_SZ + t]);
    sh[t + 128] = __half2float(hh[b * H_SZ + t + 128]);
    __syncthreads();
    float acc = 0.f;
    const float* wr = fc1w + t * H_SZ;
    #pragma unroll 8
    for (int k = 0; k < H_SZ; k++) acc += sh[k] * wr[k];
    acc += fc1b[t];
    acc = fmaxf(acc, 0.f) * fc2w[t];
    red[t] = acc;
    __syncthreads();
    for (int s = 64; s > 0; s >>= 1) {
        if (t < s) red[t] += red[t + s];
        __syncthreads();
    }
    if (t == 0) out[b] = 1.f / (1.f + expf(-(red[0] + fc2b[0])));
}

// ---------------------------------------------------------------------------
// Launch
// ---------------------------------------------------------------------------
extern "C" void kernel_launch(void* const* d_in, const int* in_sizes, int n_in,
                              void* d_out, int out_size) {
    const float* x    = (const float*)d_in[0];
    const float* wih0 = (const float*)d_in[1];
    const float* whh0 = (const float*)d_in[2];
    const float* bih0 = (const float*)d_in[3];
    const float* bhh0 = (const float*)d_in[4];
    const float* wih1 = (const float*)d_in[5];
    const float* whh1 = (const float*)d_in[6];
    const float* bih1 = (const float*)d_in[7];
    const float* bhh1 = (const float*)d_in[8];
    const float* fc1w = (const float*)d_in[9];
    const float* fc1b = (const float*)d_in[10];
    const float* fc2w = (const float*)d_in[11];
    const float* fc2b = (const float*)d_in[12];
    float* out = (float*)d_out;

    cudaFuncSetAttribute(lstm_step_mma, cudaFuncAttributeMaxDynamicSharedMemorySize, SMEM_TOTAL);

    prep_weights<<<(2 * NG * KC + 255) / 256, 256>>>(wih0, whh0, wih1, whh1);
    prep_misc<<<(2 * BH + 2 * NG + 255) / 256, 256>>>(bih0, bhh0, bih1, bhh1);
    relu_cvt<<<(T_SZ * B_SZ * (H_SZ / 4) + 255) / 256, 256>>>(x);

    dim3 grid(NG / 128, B_SZ / 128, 2);   // (8, 8, 2) = 128 CTAs x 512 threads
    for (int u = 0; u <= T_SZ; u++) lstm_step_mma<<<grid, 512, SMEM_TOTAL>>>(u);

    fc_head<<<B_SZ, 128>>>(fc1w, fc1b, fc2w, fc2b, out);
}

// round 15
// speedup vs baseline: 9.5470x; 1.1227x over previous
#include <cuda_runtime.h>
#include <cuda_fp16.h>
#include <cstdint>
#include <math.h>

#define B_SZ 1024
#define T_SZ 128
#define H_SZ 256
#define NG   1024            // 4*H
#define KC   512             // combined K (x | h)
#define BH   (B_SZ * H_SZ)
#define NCTA 128

// ---------------------------------------------------------------------------
// Static device scratch (no cudaMalloc anywhere)
// ---------------------------------------------------------------------------
__device__ __align__(16) __half g_xr  [T_SZ * BH];     // relu(x) time-major fp16
__device__ __align__(16) __half g_hs0 [T_SZ * BH];     // layer-0 h outputs fp16
__device__ __align__(16) __half g_h1  [2][BH];         // layer-1 h double buffered
__device__ __align__(16) __half g_zero_h[BH];          // never written -> zero
__device__ __align__(16) __half g_Wp[2][NG * KC];      // fp16 weights [n'][K], n'=4j+g
__device__ __align__(16) float  g_biasP[2][NG];
__device__ unsigned           g_cnt;                   // barrier arrivals
__device__ volatile unsigned  g_gen;                   // barrier generation

// ---------------------------------------------------------------------------
// PTX helpers (plain sm_100: cp.async + ldmatrix + mma.sync)
// ---------------------------------------------------------------------------
__device__ __forceinline__ uint32_t smem_u32(const void* p) {
    uint32_t a;
    asm("{ .reg .u64 t; cvta.to.shared.u64 t, %1; cvt.u32.u64 %0, t; }" : "=r"(a) : "l"(p));
    return a;
}
__device__ __forceinline__ void cpasync16(uint32_t s, const void* g) {
    asm volatile("cp.async.cg.shared.global [%0], [%1], 16;" :: "r"(s), "l"(g));
}
#define CP_COMMIT() asm volatile("cp.async.commit_group;" ::: "memory")
#define CP_WAIT1()  asm volatile("cp.async.wait_group 1;" ::: "memory")
#define CP_WAIT0()  asm volatile("cp.async.wait_group 0;" ::: "memory")

#define LDSM4(r0, r1, r2, r3, addr) asm volatile( \
    "ldmatrix.sync.aligned.m8n8.x4.shared.b16 {%0,%1,%2,%3}, [%4];" \
    : "=r"(r0), "=r"(r1), "=r"(r2), "=r"(r3) : "r"(addr))

#define MMA16816(d, a, b) asm volatile( \
    "mma.sync.aligned.m16n8k16.row.col.f32.f16.f16.f32 " \
    "{%0,%1,%2,%3}, {%4,%5,%6,%7}, {%8,%9}, {%0,%1,%2,%3};" \
    : "+f"((d)[0]), "+f"((d)[1]), "+f"((d)[2]), "+f"((d)[3]) \
    : "r"((a)[0]), "r"((a)[1]), "r"((a)[2]), "r"((a)[3]), "r"((b)[0]), "r"((b)[1]))

// ---------------------------------------------------------------------------
// SMEM layout (all dedicated regions, no aliasing):
//   B resident: 128 n'-rows x 512 K fp16, pitch 1040B  -> 133120
//   A chunks:   2 bufs x (128 rows x 128 K fp16, pitch 272) -> 2 x 34816
//   h stage:    128 rows x 32 fp16, pitch 80B -> 10240
//   bias:       128 floats -> 512
//   Pitches 1040/272 are both ≡ 16B*odd mod 128 family (word stride ≡ 4 mod 32):
//   the proven conflict-free ldmatrix pattern.
// ---------------------------------------------------------------------------
#define PITCH_A  272
#define PITCH_B  1040
#define PITCH_H  80
#define OFF_BW   0
#define A_TILE_B 34816
#define OFF_A(b) (133120 + (b) * A_TILE_B)
#define OFF_HST  202752
#define OFF_BIAS 212992
#define SMEM_TOTAL 213504

__device__ __forceinline__ float fsigm(float x) {
    x = fminf(fmaxf(x, -30.f), 30.f);
    return __fdividef(1.f, 1.f + __expf(-x));
}
__device__ __forceinline__ float ftanh(float x) {
    x = fminf(fmaxf(x, -15.f), 15.f);
    float e = __expf(2.f * x);
    return (e - 1.f) * __fdividef(1.f, e + 1.f);
}

// ---------------------------------------------------------------------------
// Prep kernels
// ---------------------------------------------------------------------------
__global__ void prep_weights(const float* __restrict__ wih0, const float* __restrict__ whh0,
                             const float* __restrict__ wih1, const float* __restrict__ whh1) {
    int id = blockIdx.x * blockDim.x + threadIdx.x;
    if (id >= 2 * NG * KC) return;
    int layer = id >> 19;
    int rem   = id & ((1 << 19) - 1);
    int np = rem >> 9;
    int k  = rem & 511;
    int j = np >> 2, g = np & 3;
    int n = g * H_SZ + j;
    const float* wih = layer ? wih1 : wih0;
    const float* whh = layer ? whh1 : whh0;
    float w = (k < H_SZ) ? wih[n * H_SZ + k] : whh[n * H_SZ + (k - H_SZ)];
    g_Wp[layer][np * KC + k] = __float2half(w);
}

__global__ void prep_bias(const float* __restrict__ bih0, const float* __restrict__ bhh0,
                          const float* __restrict__ bih1, const float* __restrict__ bhh1) {
    int id = blockIdx.x * blockDim.x + threadIdx.x;
    if (id >= 2 * NG) return;
    int layer = id >> 10;
    int np = id & 1023;
    int j = np >> 2, g = np & 3;
    int n = g * H_SZ + j;
    const float* bi = layer ? bih1 : bih0;
    const float* bh = layer ? bhh1 : bhh0;
    g_biasP[layer][np] = bi[n] + bh[n];
}

// relu + [B,T,H]->[T,B,H] + fp16 convert
__global__ void relu_cvt(const float* __restrict__ x) {
    int id = blockIdx.x * blockDim.x + threadIdx.x;
    if (id >= T_SZ * B_SZ * (H_SZ / 4)) return;
    int t   = id / (B_SZ * (H_SZ / 4));
    int rem = id % (B_SZ * (H_SZ / 4));
    int b   = rem / (H_SZ / 4);
    int e4  = rem % (H_SZ / 4);
    float4 v = *(const float4*)(x + (size_t)b * T_SZ * H_SZ + t * H_SZ + e4 * 4);
    size_t o = (size_t)t * BH + b * H_SZ + e4 * 4;
    g_xr[o]     = __float2half(fmaxf(v.x, 0.f));
    g_xr[o + 1] = __float2half(fmaxf(v.y, 0.f));
    g_xr[o + 2] = __float2half(fmaxf(v.z, 0.f));
    g_xr[o + 3] = __float2half(fmaxf(v.w, 0.f));
}

// ---------------------------------------------------------------------------
// Persistent LSTM: grid (8,8,2) = 128 CTAs, 512 threads, ALL co-resident.
// Each CTA owns (m-tile, n'-tile, layer). B weights SMEM-resident for all
// 128 steps; A streamed (BK=128, 2 bufs); c in registers; shuffle epilogue;
// software global barrier between wavefronts.
// ---------------------------------------------------------------------------
__global__ __launch_bounds__(512, 1) void lstm_persistent() {
    extern __shared__ char smem[];
    const uint32_t sb = smem_u32(smem);
    const int tid  = threadIdx.x;
    const int lane = tid & 31;
    const int wid  = tid >> 5;
    const int wm   = wid & 3;        // 4 m-warps (32 rows each)
    const int wn   = wid >> 2;       // 4 n-warps (32 cols each)
    const int layer = blockIdx.z;
    const int n0 = blockIdx.x * 128;
    const int m0 = blockIdx.y * 128;
    const int j0 = n0 >> 2;
    const __half* WP = g_Wp[layer];

    // ---- one-time: resident B (128 x 512 fp16) + bias into SMEM ----
    for (int i = tid; i < 128 * 64; i += 512) {      // 16B chunks
        int row = i >> 6, c16 = i & 63;
        cpasync16(sb + OFF_BW + row * PITCH_B + c16 * 16,
                  WP + (size_t)(n0 + row) * KC + c16 * 8);
    }
    CP_COMMIT();
    if (tid < 128) ((float*)(smem + OFF_BIAS))[tid] = g_biasP[layer][n0 + tid];
    CP_WAIT0();
    __syncthreads();

    float c_reg[2][4];
    #pragma unroll
    for (int a = 0; a < 2; a++)
        #pragma unroll
        for (int b = 0; b < 4; b++) c_reg[a][b] = 0.f;

    unsigned gen = g_gen;   // all CTAs read before anyone can advance it

    const uint32_t a_lane = (uint32_t)((lane & 15) * PITCH_A + ((lane >> 4) << 4));
    const uint32_t b_lane = (uint32_t)(((lane & 7) + ((lane >> 4) & 1) * 8) * PITCH_B +
                                       ((lane >> 3) & 1) * 16);

    #pragma unroll 1
    for (int u = 0; u <= T_SZ; u++) {
        const int t = u - layer;
        if (t >= 0 && t < T_SZ) {
            // operand sources
            const __half *xs, *hs;
            if (layer == 0) {
                xs = g_xr + (size_t)t * BH;
                hs = (t == 0) ? g_zero_h : (g_hs0 + (size_t)(t - 1) * BH);
            } else {
                xs = g_hs0 + (size_t)t * BH;
                hs = (t == 0) ? g_zero_h : g_h1[(t - 1) & 1];
            }
            __half* outp = (layer == 0) ? (g_hs0 + (size_t)t * BH) : g_h1[t & 1];

            auto load_chunk = [&](int ck) {
                const int buf = ck & 1;
                const int kk = ck * 128;
                const __half* asrc = (kk < H_SZ) ? xs : hs;
                const int koff = kk & (H_SZ - 1);
                #pragma unroll
                for (int i = 0; i < 4; i++) {
                    int idx = tid + i * 512;              // 0..2047
                    int row = idx >> 4, c16 = idx & 15;
                    size_t ga = (size_t)(m0 + row) * H_SZ + koff + c16 * 8;
                    cpasync16(sb + OFF_A(buf) + row * PITCH_A + c16 * 16, asrc + ga);
                }
                CP_COMMIT();
            };

            float acc[2][4][4];
            #pragma unroll
            for (int a = 0; a < 2; a++)
                #pragma unroll
                for (int b = 0; b < 4; b++)
                    #pragma unroll
                    for (int q = 0; q < 4; q++) acc[a][b][q] = 0.f;

            load_chunk(0);

            #pragma unroll 1
            for (int ck = 0; ck < 4; ck++) {
                const int buf = ck & 1;
                if (ck < 3) load_chunk(ck + 1);
                if (ck < 3) { CP_WAIT1(); } else { CP_WAIT0(); }
                __syncthreads();

                #pragma unroll
                for (int ks = 0; ks < 8; ks++) {
                    const uint32_t kb = (uint32_t)(ck * 256 + ks * 32);   // B byte col
                    const uint32_t ka = (uint32_t)(ks * 32);               // A byte col
                    uint32_t bf[4][2];
                    #pragma unroll
                    for (int blk = 0; blk < 2; blk++) {
                        uint32_t ad = sb + OFF_BW + (wn * 32 + blk * 16) * PITCH_B + kb + b_lane;
                        LDSM4(bf[blk * 2][0], bf[blk * 2][1],
                              bf[blk * 2 + 1][0], bf[blk * 2 + 1][1], ad);
                    }
                    uint32_t af[2][4];
                    #pragma unroll
                    for (int mf = 0; mf < 2; mf++) {
                        uint32_t ad = sb + OFF_A(buf) + (wm * 32 + mf * 16) * PITCH_A + ka + a_lane;
                        LDSM4(af[mf][0], af[mf][1], af[mf][2], af[mf][3], ad);
                    }
                    #pragma unroll
                    for (int mf = 0; mf < 2; mf++)
                        #pragma unroll
                        for (int nf = 0; nf < 4; nf++)
                            MMA16816(acc[mf][nf], af[mf], bf[nf]);
                }
                __syncthreads();
            }

            // ---- shuffle epilogue: assemble {i,f,g,o} quads in-register ----
            const bool odd = (lane & 1);
            #pragma unroll
            for (int mf = 0; mf < 2; mf++)
                #pragma unroll
                for (int nf = 0; nf < 4; nf++) {
                    float q0 = acc[mf][nf][0], q1 = acc[mf][nf][1];
                    float q2 = acc[mf][nf][2], q3 = acc[mf][nf][3];
                    float r0 = __shfl_xor_sync(0xFFFFFFFFu, odd ? q0 : q2, 1);
                    float r1 = __shfl_xor_sync(0xFFFFFFFFu, odd ? q1 : q3, 1);
                    float gi = odd ? r0 : q0;
                    float gf = odd ? r1 : q1;
                    float gg = odd ? q2 : r0;
                    float go = odd ? q3 : r1;
                    int jl = wn * 8 + nf * 2 + ((lane & 3) >> 1);          // 0..31
                    int rl = wm * 32 + mf * 16 + (lane >> 2) + (odd ? 8 : 0); // 0..127
                    float4 bq = *(const float4*)(smem + OFF_BIAS + jl * 16);
                    gi += bq.x; gf += bq.y; gg += bq.z; go += bq.w;
                    float cold = c_reg[mf][nf];
                    float cn = fsigm(gf) * cold + fsigm(gi) * ftanh(gg);
                    c_reg[mf][nf] = cn;
                    float hn = fsigm(go) * ftanh(cn);
                    *(__half*)(smem + OFF_HST + rl * PITCH_H + jl * 2) = __float2half(hn);
                }
            __syncthreads();
            // coalesced h store: 512 threads x 16B = 128 rows x 32 fp16
            {
                int row = tid >> 2, c16 = tid & 3;
                int4 v = *(const int4*)(smem + OFF_HST + row * PITCH_H + c16 * 16);
                *(int4*)(outp + (size_t)(m0 + row) * H_SZ + j0 + c16 * 8) = v;
            }
        }

        // ---- global barrier between wavefronts (ALL CTAs, every u<T_SZ) ----
        if (u < T_SZ) {
            __threadfence();          // publish this thread's h stores to L2
            __syncthreads();          // all threads fenced
            if (tid == 0) {
                unsigned arrived = atomicAdd(&g_cnt, 1);
                if (arrived == NCTA - 1) {
                    g_cnt = 0;
                    __threadfence();
                    g_gen = gen + 1;  // release
                } else {
                    while (g_gen == gen) __nanosleep(64);
                }
            }
            __syncthreads();
            gen++;
        }
    }
}

// ---------------------------------------------------------------------------
// FC head
// ---------------------------------------------------------------------------
__global__ __launch_bounds__(128) void fc_head(const float* __restrict__ fc1w,
                                               const float* __restrict__ fc1b,
                                               const float* __restrict__ fc2w,
                                               const float* __restrict__ fc2b,
                                               float* __restrict__ out) {
    __shared__ float sh[H_SZ];
    __shared__ float red[128];
    const int b = blockIdx.x, t = threadIdx.x;
    const __half* hh = g_h1[(T_SZ - 1) & 1];
    sh[t]       = __half2float(hh[b * H_SZ + t]);
    sh[t + 128] = __half2float(hh[b * H_SZ + t + 128]);
    __syncthreads();
    float acc = 0.f;
    const float* wr = fc1w + t * H_SZ;
    #pragma unroll 8
    for (int k = 0; k < H_SZ; k++) acc += sh[k] * wr[k];
    acc += fc1b[t];
    acc = fmaxf(acc, 0.f) * fc2w[t];
    red[t] = acc;
    __syncthreads();
    for (int s = 64; s > 0; s >>= 1) {
        if (t < s) red[t] += red[t + s];
        __syncthreads();
    }
    if (t == 0) out[b] = 1.f / (1.f + expf(-(red[0] + fc2b[0])));
}

// ---------------------------------------------------------------------------
// Launch
// ---------------------------------------------------------------------------
extern "C" void kernel_launch(void* const* d_in, const int* in_sizes, int n_in,
                              void* d_out, int out_size) {
    const float* x    = (const float*)d_in[0];
    const float* wih0 = (const float*)d_in[1];
    const float* whh0 = (const float*)d_in[2];
    const float* bih0 = (const float*)d_in[3];
    const float* bhh0 = (const float*)d_in[4];
    const float* wih1 = (const float*)d_in[5];
    const float* whh1 = (const float*)d_in[6];
    const float* bih1 = (const float*)d_in[7];
    const float* bhh1 = (const float*)d_in[8];
    const float* fc1w = (const float*)d_in[9];
    const float* fc1b = (const float*)d_in[10];
    const float* fc2w = (const float*)d_in[11];
    const float* fc2b = (const float*)d_in[12];
    float* out = (float*)d_out;

    cudaFuncSetAttribute(lstm_persistent, cudaFuncAttributeMaxDynamicSharedMemorySize, SMEM_TOTAL);

    prep_weights<<<(2 * NG * KC + 255) / 256, 256>>>(wih0, whh0, wih1, whh1);
    prep_bias<<<(2 * NG + 255) / 256, 256>>>(bih0, bhh0, bih1, bhh1);
    relu_cvt<<<(T_SZ * B_SZ * (H_SZ / 4) + 255) / 256, 256>>>(x);

    dim3 grid(NG / 128, B_SZ / 128, 2);   // 128 CTAs, all co-resident
    lstm_persistent<<<grid, 512, SMEM_TOTAL>>>();

    fc_head<<<B_SZ, 128>>>(fc1w, fc1b, fc2w, fc2b, out);
}